// round 1
// baseline (speedup 1.0000x reference)
#include <cuda_runtime.h>
#include <math.h>

// Problem constants
#define HDIM     256
#define BATCH    1024
#define TSTEPS   64
#define IMGD     2048
#define G4       1024   // 4*H

// Scratch (device globals; no allocation allowed)
__device__ float g_img[BATCH * HDIM];                       // relu(img @ W_img^T + b)
__device__ float g_xg[(size_t)TSTEPS * BATCH * G4];          // 268 MB input projections
__device__ float g_h[BATCH * HDIM];
__device__ float g_c[BATCH * HDIM];
__device__ float g_gates[BATCH * G4];

// ---------------------------------------------------------------------------
// Generic tiled SGEMM: C[M,N] = A[M,K] @ Bm[N,K]^T  (both row-major), fp32.
// BM=BN=64, BK=16, 256 threads, 4x4 register microtile per thread.
// MODE 0: C = relu(acc + bias[n])                          (image branch)
// MODE 1: C = acc + bias[n] + bias2[n], A row gathered      (xg projection)
// MODE 2: C = acc + addmat[m*N+n]                           (recurrent gates)
// All dims are multiples of the tile sizes for this problem; no bounds checks.
// ---------------------------------------------------------------------------
template <int MODE>
__global__ __launch_bounds__(256)
void gemm_kernel(const float* __restrict__ A,
                 const float* __restrict__ Bm,
                 float* __restrict__ C,
                 int M, int N, int K,
                 const float* __restrict__ bias,
                 const float* __restrict__ bias2,
                 const int* __restrict__ gather,
                 const float* __restrict__ addmat)
{
    const int BM = 64, BN = 64, BK = 16;
    __shared__ float As[BK][BM];
    __shared__ float Bs[BK][BN];

    const int tid = threadIdx.x;
    const int tx = tid & 15;        // 0..15
    const int ty = tid >> 4;        // 0..15
    const int m0 = blockIdx.x * BM;
    const int n0 = blockIdx.y * BN;

    // Tile-load mapping: 256 threads, each loads one float4 of A and one of B.
    const int lrow  = tid >> 2;         // 0..63  (row within tile)
    const int lcol4 = (tid & 3) * 4;    // 0,4,8,12 (starting col within BK)

    const int gm = m0 + lrow;
    const float* aptr;
    if (MODE == 1) aptr = A + (size_t)gather[gm] * K;
    else           aptr = A + (size_t)gm * K;
    const float* bptr = Bm + (size_t)(n0 + lrow) * K;

    float acc[4][4];
#pragma unroll
    for (int i = 0; i < 4; i++)
#pragma unroll
        for (int j = 0; j < 4; j++) acc[i][j] = 0.f;

    for (int k0 = 0; k0 < K; k0 += BK) {
        float4 av = *(const float4*)(aptr + k0 + lcol4);
        float4 bv = *(const float4*)(bptr + k0 + lcol4);
        As[lcol4 + 0][lrow] = av.x;
        As[lcol4 + 1][lrow] = av.y;
        As[lcol4 + 2][lrow] = av.z;
        As[lcol4 + 3][lrow] = av.w;
        Bs[lcol4 + 0][lrow] = bv.x;
        Bs[lcol4 + 1][lrow] = bv.y;
        Bs[lcol4 + 2][lrow] = bv.z;
        Bs[lcol4 + 3][lrow] = bv.w;
        __syncthreads();

#pragma unroll
        for (int k = 0; k < BK; k++) {
            float a[4], b[4];
#pragma unroll
            for (int i = 0; i < 4; i++) a[i] = As[k][ty * 4 + i];
#pragma unroll
            for (int j = 0; j < 4; j++) b[j] = Bs[k][tx * 4 + j];
#pragma unroll
            for (int i = 0; i < 4; i++)
#pragma unroll
                for (int j = 0; j < 4; j++) acc[i][j] = fmaf(a[i], b[j], acc[i][j]);
        }
        __syncthreads();
    }

#pragma unroll
    for (int i = 0; i < 4; i++) {
        const int m = m0 + ty * 4 + i;
#pragma unroll
        for (int j = 0; j < 4; j++) {
            const int n = n0 + tx * 4 + j;
            float v = acc[i][j];
            if (MODE == 0)      v = fmaxf(v + bias[n], 0.f);
            else if (MODE == 1) v = v + bias[n] + bias2[n];
            else                v = v + addmat[(size_t)m * N + n];
            C[(size_t)m * N + n] = v;
        }
    }
}

// ---------------------------------------------------------------------------
// Elementwise LSTM cell: reads g_gates [B,4H] (i,f,g,o chunks of H), updates
// g_c/g_h in place, writes out_t[b*H+j] = h_new + g_img[b*H+j].
// ---------------------------------------------------------------------------
__global__ __launch_bounds__(256)
void lstm_cell_kernel(float* __restrict__ out_t)
{
    const int idx = blockIdx.x * blockDim.x + threadIdx.x;   // 0 .. B*H-1
    const int b = idx >> 8;          // / HDIM
    const int j = idx & (HDIM - 1);

    const float* g = g_gates + (size_t)b * G4;
    const float gi = g[j];
    const float gf = g[j + HDIM];
    const float gg = g[j + 2 * HDIM];
    const float go = g[j + 3 * HDIM];

    const float i = 1.f / (1.f + expf(-gi));
    const float f = 1.f / (1.f + expf(-gf));
    const float gv = tanhf(gg);
    const float o = 1.f / (1.f + expf(-go));

    const float c_new = f * g_c[idx] + i * gv;
    const float h_new = o * tanhf(c_new);

    g_c[idx] = c_new;
    g_h[idx] = h_new;
    out_t[idx] = h_new + g_img[idx];
}

__global__ void init_hc_kernel()
{
    const int idx = blockIdx.x * blockDim.x + threadIdx.x;
    g_h[idx] = 0.f;
    g_c[idx] = 0.f;
}

// ---------------------------------------------------------------------------
// Launcher. Input order (metadata):
// 0 img_feature [B, IMGD] f32
// 1 caption_sequence [T, B] i32
// 2 W_img [H, IMGD] f32
// 3 b_img [H] f32
// 4 emb [VOCAB, H] f32
// 5 W_ih [4H, H] f32
// 6 W_hh [4H, H] f32
// 7 b_ih [4H] f32
// 8 b_hh [4H] f32
// out: [T, B, H] f32
// ---------------------------------------------------------------------------
extern "C" void kernel_launch(void* const* d_in, const int* in_sizes, int n_in,
                              void* d_out, int out_size)
{
    const float* img  = (const float*)d_in[0];
    const int*   cap  = (const int*)  d_in[1];
    const float* Wimg = (const float*)d_in[2];
    const float* bimg = (const float*)d_in[3];
    const float* emb  = (const float*)d_in[4];
    const float* Wih  = (const float*)d_in[5];
    const float* Whh  = (const float*)d_in[6];
    const float* bih  = (const float*)d_in[7];
    const float* bhh  = (const float*)d_in[8];
    float* out = (float*)d_out;

    float* p_img;   cudaGetSymbolAddress((void**)&p_img,   g_img);
    float* p_xg;    cudaGetSymbolAddress((void**)&p_xg,    g_xg);
    float* p_gates; cudaGetSymbolAddress((void**)&p_gates, g_gates);
    float* p_h;     cudaGetSymbolAddress((void**)&p_h,     g_h);

    // zero h, c
    init_hc_kernel<<<(BATCH * HDIM) / 256, 256>>>();

    // image branch: [B, H] = relu(img @ Wimg^T + bimg)
    {
        dim3 grid(BATCH / 64, HDIM / 64);
        gemm_kernel<0><<<grid, 256>>>(img, Wimg, p_img, BATCH, HDIM, IMGD,
                                      bimg, nullptr, nullptr, nullptr);
    }

    // xg: [T*B, 4H] = emb[cap] @ Wih^T + bih + bhh
    {
        dim3 grid((TSTEPS * BATCH) / 64, G4 / 64);
        gemm_kernel<1><<<grid, 256>>>(emb, Wih, p_xg, TSTEPS * BATCH, G4, HDIM,
                                      bih, bhh, cap, nullptr);
    }

    // recurrent loop
    for (int t = 0; t < TSTEPS; t++) {
        const float* xg_t = p_xg + (size_t)t * BATCH * G4;
        dim3 grid(BATCH / 64, G4 / 64);
        gemm_kernel<2><<<grid, 256>>>(p_h, Whh, p_gates, BATCH, G4, HDIM,
                                      nullptr, nullptr, nullptr, xg_t);
        lstm_cell_kernel<<<(BATCH * HDIM) / 256, 256>>>(out + (size_t)t * BATCH * HDIM);
    }
}

// round 2
// speedup vs baseline: 1.7053x; 1.7053x over previous
#include <cuda_runtime.h>
#include <math.h>

// Problem constants
#define HDIM     256
#define BATCH    1024
#define TSTEPS   64
#define IMGD     2048
#define G4       1024   // 4*H

// Scratch (device globals; no allocation allowed)
__device__ float g_img[BATCH * HDIM];
__device__ float g_xg[(size_t)TSTEPS * BATCH * G4];   // 268 MB input projections
__device__ float g_h0[BATCH * HDIM];
__device__ float g_h1[BATCH * HDIM];
__device__ float g_c[BATCH * HDIM];

// ---------------------------------------------------------------------------
// xg GEMM: C[65536,1024] = emb[cap[m]] @ Wih^T + (bih+bhh)
// 128x128 tile, BK=16, 256 threads, 8x8 microtile (split 4+4), double buffer.
// ---------------------------------------------------------------------------
__global__ __launch_bounds__(256, 2)
void xg_gemm_kernel(const float* __restrict__ emb,
                    const float* __restrict__ Wih,
                    const int* __restrict__ cap,
                    const float* __restrict__ bih,
                    const float* __restrict__ bhh,
                    float* __restrict__ C)
{
    const int N = G4, K = HDIM;
    __shared__ float As[2][16][128];
    __shared__ float Bs[2][16][128];

    const int t  = threadIdx.x;
    const int tx = t & 15;          // 0..15 -> n cols tx*4 and 64+tx*4
    const int ty = t >> 4;          // 0..15 -> m rows ty*4 and 64+ty*4
    const int m0 = blockIdx.x * 128;
    const int n0 = blockIdx.y * 128;

    const int r  = t >> 1;          // 0..127 tile row for loads
    const int c8 = (t & 1) * 8;     // 0 or 8

    const float* aptr = emb + (size_t)cap[m0 + r] * K + c8;
    const float* bptr = Wih + (size_t)(n0 + r) * K + c8;

    float acc[8][8];
#pragma unroll
    for (int i = 0; i < 8; i++)
#pragma unroll
        for (int j = 0; j < 8; j++) acc[i][j] = 0.f;

    // preload stage 0
    {
        float4 a0 = *(const float4*)(aptr);
        float4 a1 = *(const float4*)(aptr + 4);
        float4 b0 = *(const float4*)(bptr);
        float4 b1 = *(const float4*)(bptr + 4);
        As[0][c8 + 0][r] = a0.x; As[0][c8 + 1][r] = a0.y;
        As[0][c8 + 2][r] = a0.z; As[0][c8 + 3][r] = a0.w;
        As[0][c8 + 4][r] = a1.x; As[0][c8 + 5][r] = a1.y;
        As[0][c8 + 6][r] = a1.z; As[0][c8 + 7][r] = a1.w;
        Bs[0][c8 + 0][r] = b0.x; Bs[0][c8 + 1][r] = b0.y;
        Bs[0][c8 + 2][r] = b0.z; Bs[0][c8 + 3][r] = b0.w;
        Bs[0][c8 + 4][r] = b1.x; Bs[0][c8 + 5][r] = b1.y;
        Bs[0][c8 + 6][r] = b1.z; Bs[0][c8 + 7][r] = b1.w;
    }
    __syncthreads();

    int buf = 0;
    const int NST = K / 16;   // 16 stages
#pragma unroll 1
    for (int ks = 0; ks < NST; ks++) {
        float4 na0, na1, nb0, nb1;
        const bool has_next = (ks + 1 < NST);
        if (has_next) {
            const int k0 = (ks + 1) * 16;
            na0 = *(const float4*)(aptr + k0);
            na1 = *(const float4*)(aptr + k0 + 4);
            nb0 = *(const float4*)(bptr + k0);
            nb1 = *(const float4*)(bptr + k0 + 4);
        }
#pragma unroll
        for (int k = 0; k < 16; k++) {
            float a[8], b[8];
            *(float4*)(a)     = *(const float4*)&As[buf][k][ty * 4];
            *(float4*)(a + 4) = *(const float4*)&As[buf][k][64 + ty * 4];
            *(float4*)(b)     = *(const float4*)&Bs[buf][k][tx * 4];
            *(float4*)(b + 4) = *(const float4*)&Bs[buf][k][64 + tx * 4];
#pragma unroll
            for (int i = 0; i < 8; i++)
#pragma unroll
                for (int j = 0; j < 8; j++)
                    acc[i][j] = fmaf(a[i], b[j], acc[i][j]);
        }
        if (has_next) {
            const int nb = buf ^ 1;
            As[nb][c8 + 0][r] = na0.x; As[nb][c8 + 1][r] = na0.y;
            As[nb][c8 + 2][r] = na0.z; As[nb][c8 + 3][r] = na0.w;
            As[nb][c8 + 4][r] = na1.x; As[nb][c8 + 5][r] = na1.y;
            As[nb][c8 + 6][r] = na1.z; As[nb][c8 + 7][r] = na1.w;
            Bs[nb][c8 + 0][r] = nb0.x; Bs[nb][c8 + 1][r] = nb0.y;
            Bs[nb][c8 + 2][r] = nb0.z; Bs[nb][c8 + 3][r] = nb0.w;
            Bs[nb][c8 + 4][r] = nb1.x; Bs[nb][c8 + 5][r] = nb1.y;
            Bs[nb][c8 + 6][r] = nb1.z; Bs[nb][c8 + 7][r] = nb1.w;
            __syncthreads();
            buf = nb;
        }
    }

    // epilogue: + bih[n] + bhh[n]
    float bv[8];
#pragma unroll
    for (int j = 0; j < 4; j++) {
        bv[j]     = bih[n0 + tx * 4 + j]      + bhh[n0 + tx * 4 + j];
        bv[4 + j] = bih[n0 + 64 + tx * 4 + j] + bhh[n0 + 64 + tx * 4 + j];
    }
#pragma unroll
    for (int i = 0; i < 8; i++) {
        const int m = m0 + ((i < 4) ? (ty * 4 + i) : (64 + ty * 4 + (i - 4)));
        float4 v0, v1;
        v0.x = acc[i][0] + bv[0]; v0.y = acc[i][1] + bv[1];
        v0.z = acc[i][2] + bv[2]; v0.w = acc[i][3] + bv[3];
        v1.x = acc[i][4] + bv[4]; v1.y = acc[i][5] + bv[5];
        v1.z = acc[i][6] + bv[6]; v1.w = acc[i][7] + bv[7];
        *(float4*)&C[(size_t)m * N + n0 + tx * 4]      = v0;
        *(float4*)&C[(size_t)m * N + n0 + 64 + tx * 4] = v1;
    }
}

// ---------------------------------------------------------------------------
// Image branch: g_img[B,H] = relu(img @ Wimg^T + bimg). 64x64 tile (round-0).
// ---------------------------------------------------------------------------
__global__ __launch_bounds__(256)
void img_gemm_kernel(const float* __restrict__ A,
                     const float* __restrict__ Bm,
                     float* __restrict__ C,
                     const float* __restrict__ bias)
{
    const int N = HDIM, K = IMGD;
    const int BK = 16;
    __shared__ float As[16][64];
    __shared__ float Bs[16][64];

    const int tid = threadIdx.x;
    const int tx = tid & 15;
    const int ty = tid >> 4;
    const int m0 = blockIdx.x * 64;
    const int n0 = blockIdx.y * 64;

    const int lrow  = tid >> 2;
    const int lcol4 = (tid & 3) * 4;

    const float* aptr = A + (size_t)(m0 + lrow) * K;
    const float* bptr = Bm + (size_t)(n0 + lrow) * K;

    float acc[4][4];
#pragma unroll
    for (int i = 0; i < 4; i++)
#pragma unroll
        for (int j = 0; j < 4; j++) acc[i][j] = 0.f;

    for (int k0 = 0; k0 < K; k0 += BK) {
        float4 av = *(const float4*)(aptr + k0 + lcol4);
        float4 bv = *(const float4*)(bptr + k0 + lcol4);
        As[lcol4 + 0][lrow] = av.x; As[lcol4 + 1][lrow] = av.y;
        As[lcol4 + 2][lrow] = av.z; As[lcol4 + 3][lrow] = av.w;
        Bs[lcol4 + 0][lrow] = bv.x; Bs[lcol4 + 1][lrow] = bv.y;
        Bs[lcol4 + 2][lrow] = bv.z; Bs[lcol4 + 3][lrow] = bv.w;
        __syncthreads();
#pragma unroll
        for (int k = 0; k < BK; k++) {
            float a[4], b[4];
            *(float4*)a = *(const float4*)&As[k][ty * 4];
            *(float4*)b = *(const float4*)&Bs[k][tx * 4];
#pragma unroll
            for (int i = 0; i < 4; i++)
#pragma unroll
                for (int j = 0; j < 4; j++) acc[i][j] = fmaf(a[i], b[j], acc[i][j]);
        }
        __syncthreads();
    }
#pragma unroll
    for (int i = 0; i < 4; i++) {
        const int m = m0 + ty * 4 + i;
#pragma unroll
        for (int j = 0; j < 4; j++) {
            const int n = n0 + tx * 4 + j;
            C[(size_t)m * N + n] = fmaxf(acc[i][j] + bias[n], 0.f);
        }
    }
}

// ---------------------------------------------------------------------------
// Fused recurrent step: per block a 32(batch) x 32(Hcols) tile, all 4 gates.
// gates = h_read @ Whh^T (+ xg_t which already has both biases), then cell:
//   c = f*c + i*g; h = o*tanh(c); out = h + img
// h is double-buffered across steps (h_read -> h_write).
// Grid (32, 8) = 256 blocks, 128 threads.
// ---------------------------------------------------------------------------
__global__ __launch_bounds__(128)
void lstm_step_kernel(const float* __restrict__ Whh,
                      const float* __restrict__ xg_t,
                      const float* __restrict__ h_read,
                      float* __restrict__ h_write,
                      float* __restrict__ out_t)
{
    __shared__ float As[2][16][32];
    __shared__ float Bs[2][4][16][32];

    const int t  = threadIdx.x;
    const int tx = t & 15;        // n = n0 + tx*2 + {0,1}
    const int ty = t >> 4;        // 0..7, m = m0 + ty*4 + {0..3}
    const int m0 = blockIdx.x * 32;
    const int n0 = blockIdx.y * 32;

    const int r  = t >> 2;        // 0..31
    const int c4 = (t & 3) * 4;   // 0,4,8,12

    const float* aptr = h_read + (size_t)(m0 + r) * HDIM + c4;
    const float* bptr = Whh + (size_t)(n0 + r) * HDIM + c4;   // gate q: + q*HDIM*HDIM

    float acc[4][4][2];
#pragma unroll
    for (int q = 0; q < 4; q++)
#pragma unroll
        for (int i = 0; i < 4; i++) { acc[q][i][0] = 0.f; acc[q][i][1] = 0.f; }

    // preload stage 0
    {
        float4 av = *(const float4*)(aptr);
        As[0][c4 + 0][r] = av.x; As[0][c4 + 1][r] = av.y;
        As[0][c4 + 2][r] = av.z; As[0][c4 + 3][r] = av.w;
#pragma unroll
        for (int q = 0; q < 4; q++) {
            float4 bv = *(const float4*)(bptr + (size_t)q * HDIM * HDIM);
            Bs[0][q][c4 + 0][r] = bv.x; Bs[0][q][c4 + 1][r] = bv.y;
            Bs[0][q][c4 + 2][r] = bv.z; Bs[0][q][c4 + 3][r] = bv.w;
        }
    }
    __syncthreads();

    int buf = 0;
    const int NST = HDIM / 16;  // 16
#pragma unroll 1
    for (int ks = 0; ks < NST; ks++) {
        float4 nav, nbv[4];
        const bool has_next = (ks + 1 < NST);
        if (has_next) {
            const int k0 = (ks + 1) * 16;
            nav = *(const float4*)(aptr + k0);
#pragma unroll
            for (int q = 0; q < 4; q++)
                nbv[q] = *(const float4*)(bptr + (size_t)q * HDIM * HDIM + k0);
        }
#pragma unroll
        for (int k = 0; k < 16; k++) {
            float a[4];
            *(float4*)a = *(const float4*)&As[buf][k][ty * 4];
            float b[4][2];
#pragma unroll
            for (int q = 0; q < 4; q++) {
                float2 bb = *(const float2*)&Bs[buf][q][k][tx * 2];
                b[q][0] = bb.x; b[q][1] = bb.y;
            }
#pragma unroll
            for (int q = 0; q < 4; q++)
#pragma unroll
                for (int i = 0; i < 4; i++) {
                    acc[q][i][0] = fmaf(a[i], b[q][0], acc[q][i][0]);
                    acc[q][i][1] = fmaf(a[i], b[q][1], acc[q][i][1]);
                }
        }
        if (has_next) {
            const int nb = buf ^ 1;
            As[nb][c4 + 0][r] = nav.x; As[nb][c4 + 1][r] = nav.y;
            As[nb][c4 + 2][r] = nav.z; As[nb][c4 + 3][r] = nav.w;
#pragma unroll
            for (int q = 0; q < 4; q++) {
                Bs[nb][q][c4 + 0][r] = nbv[q].x; Bs[nb][q][c4 + 1][r] = nbv[q].y;
                Bs[nb][q][c4 + 2][r] = nbv[q].z; Bs[nb][q][c4 + 3][r] = nbv[q].w;
            }
            __syncthreads();
            buf = nb;
        }
    }

    // epilogue: LSTM cell + broadcast add
#pragma unroll
    for (int i = 0; i < 4; i++) {
#pragma unroll
        for (int j = 0; j < 2; j++) {
            const int m = m0 + ty * 4 + i;
            const int n = n0 + tx * 2 + j;
            const size_t xb = (size_t)m * G4 + n;
            const float gi = acc[0][i][j] + xg_t[xb];
            const float gf = acc[1][i][j] + xg_t[xb + HDIM];
            const float gg = acc[2][i][j] + xg_t[xb + 2 * HDIM];
            const float go = acc[3][i][j] + xg_t[xb + 3 * HDIM];

            const float ii = 1.f / (1.f + expf(-gi));
            const float ff = 1.f / (1.f + expf(-gf));
            const float gv = tanhf(gg);
            const float oo = 1.f / (1.f + expf(-go));

            const int idx = m * HDIM + n;
            const float cn = ff * g_c[idx] + ii * gv;
            const float hn = oo * tanhf(cn);
            g_c[idx] = cn;
            h_write[idx] = hn;
            out_t[idx] = hn + g_img[idx];
        }
    }
}

__global__ void init_hc_kernel()
{
    const int idx = blockIdx.x * blockDim.x + threadIdx.x;
    g_h0[idx] = 0.f;
    g_c[idx] = 0.f;
}

// ---------------------------------------------------------------------------
extern "C" void kernel_launch(void* const* d_in, const int* in_sizes, int n_in,
                              void* d_out, int out_size)
{
    const float* img  = (const float*)d_in[0];
    const int*   cap  = (const int*)  d_in[1];
    const float* Wimg = (const float*)d_in[2];
    const float* bimg = (const float*)d_in[3];
    const float* emb  = (const float*)d_in[4];
    const float* Wih  = (const float*)d_in[5];
    const float* Whh  = (const float*)d_in[6];
    const float* bih  = (const float*)d_in[7];
    const float* bhh  = (const float*)d_in[8];
    float* out = (float*)d_out;

    float* p_img; cudaGetSymbolAddress((void**)&p_img, g_img);
    float* p_xg;  cudaGetSymbolAddress((void**)&p_xg,  g_xg);
    float* p_h0;  cudaGetSymbolAddress((void**)&p_h0,  g_h0);
    float* p_h1;  cudaGetSymbolAddress((void**)&p_h1,  g_h1);

    init_hc_kernel<<<(BATCH * HDIM) / 256, 256>>>();

    {
        dim3 grid(BATCH / 64, HDIM / 64);
        img_gemm_kernel<<<grid, 256>>>(img, Wimg, p_img, bimg);
    }

    {
        dim3 grid((TSTEPS * BATCH) / 128, G4 / 128);
        xg_gemm_kernel<<<grid, 256>>>(emb, Wih, cap, bih, bhh, p_xg);
    }

    float* hbuf[2] = {p_h0, p_h1};
    for (int tstep = 0; tstep < TSTEPS; tstep++) {
        const float* xg_t = p_xg + (size_t)tstep * BATCH * G4;
        dim3 grid(BATCH / 32, HDIM / 32);
        lstm_step_kernel<<<grid, 128>>>(Whh, xg_t,
                                        hbuf[tstep & 1], hbuf[(tstep & 1) ^ 1],
                                        out + (size_t)tstep * BATCH * HDIM);
    }
}

// round 4
// speedup vs baseline: 1.8635x; 1.0928x over previous
#include <cuda_runtime.h>
#include <cuda_bf16.h>
#include <math.h>
#include <stdint.h>

#define HDIM   256
#define BATCH  1024
#define TSTEPS 64
#define IMGD   2048
#define G4     1024
#define VOCAB  32000

// ---------------- device scratch (no allocation allowed) -------------------
__device__ float g_img[BATCH * HDIM];
__device__ float g_xg[(size_t)TSTEPS * BATCH * G4];          // permuted gate cols
__device__ __nv_bfloat16 g_ehi[(size_t)VOCAB * HDIM];
__device__ __nv_bfloat16 g_elo[(size_t)VOCAB * HDIM];
__device__ __nv_bfloat16 g_wih[G4 * 2 * HDIM];               // [p][0:256]=hi, [256:512]=lo
__device__ __nv_bfloat16 g_whh[G4 * 2 * HDIM];
__device__ float g_biasp[G4];
__device__ __nv_bfloat16 g_hhi[2][BATCH * HDIM];
__device__ __nv_bfloat16 g_hlo[2][BATCH * HDIM];
__device__ float g_c[BATCH * HDIM];

// ---------------- helpers ---------------------------------------------------
__device__ __forceinline__ uint32_t smem_u32(const void* p) {
    uint32_t a;
    asm("{ .reg .u64 t; cvta.to.shared.u64 t, %1; cvt.u32.u64 %0, t; }" : "=r"(a) : "l"(p));
    return a;
}
__device__ __forceinline__ void cp_async16(uint32_t saddr, const void* gaddr) {
    asm volatile("cp.async.cg.shared.global [%0], [%1], 16;" :: "r"(saddr), "l"(gaddr));
}
__device__ __forceinline__ void ldm_x4(uint32_t* r, uint32_t addr) {
    asm volatile("ldmatrix.sync.aligned.m8n8.x4.shared.b16 {%0,%1,%2,%3}, [%4];"
                 : "=r"(r[0]), "=r"(r[1]), "=r"(r[2]), "=r"(r[3]) : "r"(addr));
}
__device__ __forceinline__ void ldm_x2(uint32_t* r, uint32_t addr) {
    asm volatile("ldmatrix.sync.aligned.m8n8.x2.shared.b16 {%0,%1}, [%2];"
                 : "=r"(r[0]), "=r"(r[1]) : "r"(addr));
}
__device__ __forceinline__ void mma_bf16(float* d, const uint32_t* a, const uint32_t* b) {
    asm volatile("mma.sync.aligned.m16n8k16.row.col.f32.bf16.bf16.f32 "
                 "{%0,%1,%2,%3}, {%4,%5,%6,%7}, {%8,%9}, {%0,%1,%2,%3};"
                 : "+f"(d[0]), "+f"(d[1]), "+f"(d[2]), "+f"(d[3])
                 : "r"(a[0]), "r"(a[1]), "r"(a[2]), "r"(a[3]), "r"(b[0]), "r"(b[1]));
}

// ---------------- bf16-split tensor-core GEMM -------------------------------
// D[m][n] = sum_k A[m][k]*B[n][k], fp32 via bf16 hi/lo split.
// A: (Ahi, Alo) row stride 256. B prepacked [1024][512]: 0:256 hi, 256:512 lo.
// 12 K-chunks of 64: c>>2 == 0: Ahi*Bhi, 1: Alo*Bhi, 2: Ahi*Blo.
// CTA 128x128, 256 thr, 8 warps (2 M x 4 N), warp tile 64x32. cp.async 2-stage.
// EPI 0: D + biasp -> Cout (xg). EPI 1: fused LSTM cell.
#define STG_BYTES 32768           // A 16KB + B 16KB per stage
#define MMA_SMEM  (2 * STG_BYTES)

template <int EPI>
__global__ __launch_bounds__(256)
void mma_gemm_kernel(const __nv_bfloat16* __restrict__ Ahi,
                     const __nv_bfloat16* __restrict__ Alo,
                     const __nv_bfloat16* __restrict__ Bw,
                     const int* __restrict__ gather,
                     const float* __restrict__ xg_t,
                     float* __restrict__ Cout,
                     __nv_bfloat16* __restrict__ hhi_w,
                     __nv_bfloat16* __restrict__ hlo_w)
{
    extern __shared__ __align__(1024) char smem[];
    const uint32_t sbase = smem_u32(smem);
    const int t = threadIdx.x;
    const int lane = t & 31;
    const int wid = t >> 5;
    const int wm = wid >> 2;           // 0..1 (64 rows each)
    const int wn = wid & 3;            // 0..3
    const int m0 = blockIdx.x * 128;
    const int n0 = blockIdx.y * 128;

    // ---- load-side mapping: thread -> (row lr, half) ; 4x16B per operand ----
    const int lr = t >> 1;
    const int lhalf = t & 1;
    const int arow = (EPI == 0) ? gather[m0 + lr] : (m0 + lr);
    const __nv_bfloat16* a_hi = Ahi + (size_t)arow * HDIM;
    const __nv_bfloat16* a_lo = Alo + (size_t)arow * HDIM;
    const __nv_bfloat16* b_row = Bw + (size_t)(n0 + lr) * (2 * HDIM);

    uint32_t sdst[4];                  // swizzled dst byte offsets within a stage
#pragma unroll
    for (int i = 0; i < 4; ++i) {
        const int w = lhalf * 4 + i;
        sdst[i] = (uint32_t)((lr * 8 + (w ^ (lr & 7))) * 16);
    }

    // ---- mma-side fragment row indices (fixed per thread) ----
    int rA[4], rB[4];
    const int mtx = lane >> 3;         // 0..3
    const int mhi = lane >> 4;         // k-high selector for A
    const int mB  = (lane >> 3) & 1;   // k-high selector for B
#pragma unroll
    for (int mf = 0; mf < 4; ++mf)
        rA[mf] = wm * 64 + mf * 16 + (mtx & 1) * 8 + (lane & 7);
#pragma unroll
    for (int q = 0; q < 4; ++q) {
        const int nbase = (EPI == 0) ? (wn * 32 + q * 8) : (q * 32 + wn * 8);
        rB[q] = nbase + (lane & 7);
    }

    float acc[4][4][4];
#pragma unroll
    for (int i = 0; i < 4; ++i)
#pragma unroll
        for (int j = 0; j < 4; ++j)
#pragma unroll
            for (int r = 0; r < 4; ++r) acc[i][j][r] = 0.f;

    // ---- async copy of one chunk into a stage ----
    auto issue = [&](int c, int s) {
        const int kcol = (c & 3) * 64;
        const __nv_bfloat16* asrc = (((c >> 2) == 1) ? a_lo : a_hi) + kcol;
        const __nv_bfloat16* bsrc = b_row + kcol + (((c >> 2) == 2) ? 256 : 0);
        const uint32_t sa = sbase + s * STG_BYTES;
        const uint32_t sb = sa + 16384;
#pragma unroll
        for (int i = 0; i < 4; ++i) {
            const int e = (lhalf * 4 + i) * 8;
            cp_async16(sa + sdst[i], asrc + e);
            cp_async16(sb + sdst[i], bsrc + e);
        }
        asm volatile("cp.async.commit_group;" ::: "memory");
    };

    issue(0, 0);

#pragma unroll 1
    for (int c = 0; c < 12; ++c) {
        if (c < 11) {
            issue(c + 1, (c + 1) & 1);
            asm volatile("cp.async.wait_group 1;" ::: "memory");
        } else {
            asm volatile("cp.async.wait_group 0;" ::: "memory");
        }
        __syncthreads();

        const uint32_t sa = sbase + (c & 1) * STG_BYTES;
        const uint32_t sb = sa + 16384;
#pragma unroll
        for (int ks = 0; ks < 4; ++ks) {
            uint32_t afr[4][4], bfr[4][2];
#pragma unroll
            for (int mf = 0; mf < 4; ++mf) {
                const int r = rA[mf];
                ldm_x4(afr[mf], sa + (uint32_t)((r * 8 + ((ks * 2 + mhi) ^ (r & 7))) * 16));
            }
#pragma unroll
            for (int q = 0; q < 4; ++q) {
                const int r = rB[q];
                ldm_x2(bfr[q], sb + (uint32_t)((r * 8 + ((ks * 2 + mB) ^ (r & 7))) * 16));
            }
#pragma unroll
            for (int mf = 0; mf < 4; ++mf)
#pragma unroll
                for (int q = 0; q < 4; ++q)
                    mma_bf16(acc[mf][q], afr[mf], bfr[q]);
        }
        __syncthreads();
    }

    // ---- epilogues ----
    if (EPI == 0) {
        const int mrow = m0 + wm * 64 + (lane >> 2);
        const int nco  = n0 + wn * 32 + (lane & 3) * 2;
#pragma unroll
        for (int q = 0; q < 4; ++q) {
            const float bp0 = g_biasp[nco + q * 8];
            const float bp1 = g_biasp[nco + q * 8 + 1];
#pragma unroll
            for (int mf = 0; mf < 4; ++mf) {
                const int m = mrow + mf * 16;
                float2 v0 = make_float2(acc[mf][q][0] + bp0, acc[mf][q][1] + bp1);
                float2 v1 = make_float2(acc[mf][q][2] + bp0, acc[mf][q][3] + bp1);
                *(float2*)&Cout[(size_t)m * G4 + nco + q * 8] = v0;
                *(float2*)&Cout[(size_t)(m + 8) * G4 + nco + q * 8] = v1;
            }
        }
    } else {
        // each thread's fragment holds all 4 gates of (m, j)
        const int jl0 = wn * 8 + (lane & 3) * 2;
        const int hcol = blockIdx.y * 32;
#pragma unroll
        for (int mf = 0; mf < 4; ++mf) {
#pragma unroll
            for (int h = 0; h < 2; ++h) {
                const int m = m0 + wm * 64 + mf * 16 + (lane >> 2) + h * 8;
                const float* xr = xg_t + (size_t)m * G4 + n0;
#pragma unroll
                for (int jj = 0; jj < 2; ++jj) {
                    const int jl = jl0 + jj;
                    const int rsel = h * 2 + jj;
                    const float gi = acc[mf][0][rsel] + xr[jl];
                    const float gf = acc[mf][1][rsel] + xr[32 + jl];
                    const float gg = acc[mf][2][rsel] + xr[64 + jl];
                    const float go = acc[mf][3][rsel] + xr[96 + jl];
                    const float iv = 1.f / (1.f + expf(-gi));
                    const float fv = 1.f / (1.f + expf(-gf));
                    const float gv = tanhf(gg);
                    const float ov = 1.f / (1.f + expf(-go));
                    const int idx = m * HDIM + hcol + jl;
                    const float cn = fv * g_c[idx] + iv * gv;
                    const float hn = ov * tanhf(cn);
                    g_c[idx] = cn;
                    const __nv_bfloat16 hh = __float2bfloat16(hn);
                    hhi_w[idx] = hh;
                    hlo_w[idx] = __float2bfloat16(hn - __bfloat162float(hh));
                    Cout[idx] = hn + g_img[idx];
                }
            }
        }
    }
}

// ---------------- prepack / init kernels ------------------------------------
__global__ void split_emb_kernel(const float* __restrict__ emb)
{
    const size_t i = (size_t)blockIdx.x * 256 + threadIdx.x;
    const float v = emb[i];
    const __nv_bfloat16 h = __float2bfloat16(v);
    g_ehi[i] = h;
    g_elo[i] = __float2bfloat16(v - __bfloat162float(h));
}

// permuted split weights: row p <- W[orig(p)], p = nt*128 + q*32 + j, orig = q*256 + nt*32 + j
__global__ void prep_w_kernel(const float* __restrict__ W, __nv_bfloat16* __restrict__ Wd)
{
    const int i = blockIdx.x * 256 + threadIdx.x;   // [0, 1024*256)
    const int p = i >> 8, k = i & 255;
    const int nt = p >> 7, q = (p >> 5) & 3, j = p & 31;
    const int orig = q * 256 + nt * 32 + j;
    const float v = W[orig * 256 + k];
    const __nv_bfloat16 h = __float2bfloat16(v);
    Wd[p * 512 + k] = h;
    Wd[p * 512 + 256 + k] = __float2bfloat16(v - __bfloat162float(h));
}

__global__ void prep_bias_kernel(const float* __restrict__ bih, const float* __restrict__ bhh)
{
    const int p = blockIdx.x * 256 + threadIdx.x;
    const int nt = p >> 7, q = (p >> 5) & 3, j = p & 31;
    const int orig = q * 256 + nt * 32 + j;
    g_biasp[p] = bih[orig] + bhh[orig];
}

__global__ void init_state_kernel()
{
    const int i = blockIdx.x * 256 + threadIdx.x;
    g_c[i] = 0.f;
    g_hhi[0][i] = __float2bfloat16(0.f);
    g_hlo[0][i] = __float2bfloat16(0.f);
}

// ---------------- fp32 image GEMM (small) ------------------------------------
__global__ __launch_bounds__(256)
void img_gemm_kernel(const float* __restrict__ A, const float* __restrict__ Bm,
                     float* __restrict__ C, const float* __restrict__ bias)
{
    const int N = HDIM, K = IMGD;
    __shared__ float As[16][64];
    __shared__ float Bs[16][64];
    const int tid = threadIdx.x;
    const int tx = tid & 15, ty = tid >> 4;
    const int m0 = blockIdx.x * 64, n0 = blockIdx.y * 64;
    const int lrow = tid >> 2, lcol4 = (tid & 3) * 4;
    const float* aptr = A + (size_t)(m0 + lrow) * K;
    const float* bptr = Bm + (size_t)(n0 + lrow) * K;
    float acc[4][4];
#pragma unroll
    for (int i = 0; i < 4; i++)
#pragma unroll
        for (int j = 0; j < 4; j++) acc[i][j] = 0.f;
    for (int k0 = 0; k0 < K; k0 += 16) {
        float4 av = *(const float4*)(aptr + k0 + lcol4);
        float4 bv = *(const float4*)(bptr + k0 + lcol4);
        As[lcol4 + 0][lrow] = av.x; As[lcol4 + 1][lrow] = av.y;
        As[lcol4 + 2][lrow] = av.z; As[lcol4 + 3][lrow] = av.w;
        Bs[lcol4 + 0][lrow] = bv.x; Bs[lcol4 + 1][lrow] = bv.y;
        Bs[lcol4 + 2][lrow] = bv.z; Bs[lcol4 + 3][lrow] = bv.w;
        __syncthreads();
#pragma unroll
        for (int k = 0; k < 16; k++) {
            float a[4], b[4];
            *(float4*)a = *(const float4*)&As[k][ty * 4];
            *(float4*)b = *(const float4*)&Bs[k][tx * 4];
#pragma unroll
            for (int i = 0; i < 4; i++)
#pragma unroll
                for (int j = 0; j < 4; j++) acc[i][j] = fmaf(a[i], b[j], acc[i][j]);
        }
        __syncthreads();
    }
#pragma unroll
    for (int i = 0; i < 4; i++)
#pragma unroll
        for (int j = 0; j < 4; j++)
            C[(size_t)(m0 + ty * 4 + i) * N + n0 + tx * 4 + j] =
                fmaxf(acc[i][j] + bias[n0 + tx * 4 + j], 0.f);
}

// ---------------- launcher ---------------------------------------------------
extern "C" void kernel_launch(void* const* d_in, const int* in_sizes, int n_in,
                              void* d_out, int out_size)
{
    const float* img  = (const float*)d_in[0];
    const int*   cap  = (const int*)  d_in[1];
    const float* Wimg = (const float*)d_in[2];
    const float* bimg = (const float*)d_in[3];
    const float* emb  = (const float*)d_in[4];
    const float* Wih  = (const float*)d_in[5];
    const float* Whh  = (const float*)d_in[6];
    const float* bih  = (const float*)d_in[7];
    const float* bhh  = (const float*)d_in[8];
    float* out = (float*)d_out;

    float* p_img; cudaGetSymbolAddress((void**)&p_img, g_img);
    float* p_xg;  cudaGetSymbolAddress((void**)&p_xg,  g_xg);
    __nv_bfloat16* p_ehi; cudaGetSymbolAddress((void**)&p_ehi, g_ehi);
    __nv_bfloat16* p_elo; cudaGetSymbolAddress((void**)&p_elo, g_elo);
    __nv_bfloat16* p_wih; cudaGetSymbolAddress((void**)&p_wih, g_wih);
    __nv_bfloat16* p_whh; cudaGetSymbolAddress((void**)&p_whh, g_whh);
    __nv_bfloat16* p_hhi; cudaGetSymbolAddress((void**)&p_hhi, g_hhi);
    __nv_bfloat16* p_hlo; cudaGetSymbolAddress((void**)&p_hlo, g_hlo);

    cudaFuncSetAttribute(mma_gemm_kernel<0>, cudaFuncAttributeMaxDynamicSharedMemorySize, MMA_SMEM);
    cudaFuncSetAttribute(mma_gemm_kernel<1>, cudaFuncAttributeMaxDynamicSharedMemorySize, MMA_SMEM);

    // prepacks
    split_emb_kernel<<<(VOCAB * HDIM) / 256, 256>>>(emb);
    prep_w_kernel<<<(G4 * HDIM) / 256, 256>>>(Wih, p_wih);
    prep_w_kernel<<<(G4 * HDIM) / 256, 256>>>(Whh, p_whh);
    prep_bias_kernel<<<G4 / 256, 256>>>(bih, bhh);
    init_state_kernel<<<(BATCH * HDIM) / 256, 256>>>();

    // image branch (fp32)
    {
        dim3 grid(BATCH / 64, HDIM / 64);
        img_gemm_kernel<<<grid, 256>>>(img, Wimg, p_img, bimg);
    }

    // xg = emb[cap] @ Wih'^T + biasp  (permuted cols)
    {
        dim3 grid((TSTEPS * BATCH) / 128, G4 / 128);
        mma_gemm_kernel<0><<<grid, 256, MMA_SMEM>>>(p_ehi, p_elo, p_wih, cap,
                                                    nullptr, p_xg, nullptr, nullptr);
    }

    // recurrence: fused MMA + LSTM cell per step
    const size_t hsz = (size_t)BATCH * HDIM;
    for (int t = 0; t < TSTEPS; ++t) {
        const int rb = t & 1, wb = rb ^ 1;
        dim3 grid(BATCH / 128, G4 / 128);
        mma_gemm_kernel<1><<<grid, 256, MMA_SMEM>>>(
            p_hhi + (size_t)rb * hsz, p_hlo + (size_t)rb * hsz, p_whh, nullptr,
            p_xg + (size_t)t * BATCH * G4,
            out + (size_t)t * hsz,
            p_hhi + (size_t)wb * hsz, p_hlo + (size_t)wb * hsz);
    }
}

// round 5
// speedup vs baseline: 2.7411x; 1.4709x over previous
#include <cuda_runtime.h>
#include <cuda_bf16.h>
#include <math.h>
#include <stdint.h>

#define HDIM   256
#define BATCH  1024
#define TSTEPS 64
#define IMGD   2048
#define G4     1024
#define VOCAB  32000

// ---------------- device scratch (no allocation allowed) -------------------
__device__ float g_img[BATCH * HDIM];
__device__ float g_xg[(size_t)TSTEPS * BATCH * G4];          // permuted gate cols
__device__ __nv_bfloat16 g_ehi[(size_t)VOCAB * HDIM];
__device__ __nv_bfloat16 g_elo[(size_t)VOCAB * HDIM];
__device__ __nv_bfloat16 g_wih[G4 * 2 * HDIM];               // [p][0:256]=hi, [256:512]=lo
__device__ __nv_bfloat16 g_whh[G4 * 2 * HDIM];
__device__ float g_biasp[G4];
__device__ __nv_bfloat16 g_hhi[2][BATCH * HDIM];
__device__ __nv_bfloat16 g_hlo[2][BATCH * HDIM];
__device__ float g_c[BATCH * HDIM];

// grid-barrier state (zero-initialized; returns to 0 count after each use)
__device__ int g_bar_count;
__device__ volatile unsigned g_bar_gen;

// ---------------- helpers ---------------------------------------------------
__device__ __forceinline__ uint32_t smem_u32(const void* p) {
    uint32_t a;
    asm("{ .reg .u64 t; cvta.to.shared.u64 t, %1; cvt.u32.u64 %0, t; }" : "=r"(a) : "l"(p));
    return a;
}
__device__ __forceinline__ void cp_async16(uint32_t saddr, const void* gaddr) {
    asm volatile("cp.async.cg.shared.global [%0], [%1], 16;" :: "r"(saddr), "l"(gaddr));
}
__device__ __forceinline__ void ldm_x4(uint32_t* r, uint32_t addr) {
    asm volatile("ldmatrix.sync.aligned.m8n8.x4.shared.b16 {%0,%1,%2,%3}, [%4];"
                 : "=r"(r[0]), "=r"(r[1]), "=r"(r[2]), "=r"(r[3]) : "r"(addr));
}
__device__ __forceinline__ void ldm_x2(uint32_t* r, uint32_t addr) {
    asm volatile("ldmatrix.sync.aligned.m8n8.x2.shared.b16 {%0,%1}, [%2];"
                 : "=r"(r[0]), "=r"(r[1]) : "r"(addr));
}
__device__ __forceinline__ void mma_bf16(float* d, const uint32_t* a, const uint32_t* b) {
    asm volatile("mma.sync.aligned.m16n8k16.row.col.f32.bf16.bf16.f32 "
                 "{%0,%1,%2,%3}, {%4,%5,%6,%7}, {%8,%9}, {%0,%1,%2,%3};"
                 : "+f"(d[0]), "+f"(d[1]), "+f"(d[2]), "+f"(d[3])
                 : "r"(a[0]), "r"(a[1]), "r"(a[2]), "r"(a[3]), "r"(b[0]), "r"(b[1]));
}

__device__ __forceinline__ void grid_barrier() {
    __threadfence();
    __syncthreads();
    if (threadIdx.x == 0) {
        unsigned gen = g_bar_gen;
        if (atomicAdd(&g_bar_count, 1) == (int)gridDim.x - 1) {
            g_bar_count = 0;
            __threadfence();
            g_bar_gen = gen + 1;
        } else {
            while (g_bar_gen == gen) __nanosleep(32);
        }
        __threadfence();
    }
    __syncthreads();
}

// ---------------- xg GEMM: bf16-split tensor-core ---------------------------
// D[m][n] = sum_k A[m][k]*B[n][k]; 12 K-chunks of 64 (Ahi*Bhi, Alo*Bhi, Ahi*Blo).
// CTA 128x128, 256 thr, warp tile 64x32. 3-stage cp.async ring, 1 sync/chunk.
#define STG_BYTES 32768
#define XG_SMEM   (3 * STG_BYTES)

__global__ __launch_bounds__(256)
void xg_mma_kernel(const int* __restrict__ gather, float* __restrict__ Cout)
{
    extern __shared__ __align__(1024) char smem[];
    const uint32_t sbase = smem_u32(smem);
    const int t = threadIdx.x;
    const int lane = t & 31;
    const int wid = t >> 5;
    const int wm = wid >> 2;           // 0..1
    const int wn = wid & 3;            // 0..3
    const int m0 = blockIdx.x * 128;
    const int n0 = blockIdx.y * 128;

    const int lr = t >> 1;
    const int lhalf = t & 1;
    const int arow = gather[m0 + lr];
    const __nv_bfloat16* a_hi = g_ehi + (size_t)arow * HDIM;
    const __nv_bfloat16* a_lo = g_elo + (size_t)arow * HDIM;
    const __nv_bfloat16* b_row = g_wih + (size_t)(n0 + lr) * (2 * HDIM);

    uint32_t sdst[4];
#pragma unroll
    for (int i = 0; i < 4; ++i) {
        const int w = lhalf * 4 + i;
        sdst[i] = (uint32_t)((lr * 8 + (w ^ (lr & 7))) * 16);
    }

    int rA[4], rB[4];
    const int mhi = lane >> 4;
    const int mB  = (lane >> 3) & 1;
#pragma unroll
    for (int mf = 0; mf < 4; ++mf)
        rA[mf] = wm * 64 + mf * 16 + ((lane >> 3) & 1) * 8 + (lane & 7);
#pragma unroll
    for (int q = 0; q < 4; ++q)
        rB[q] = wn * 32 + q * 8 + (lane & 7);

    float acc[4][4][4];
#pragma unroll
    for (int i = 0; i < 4; ++i)
#pragma unroll
        for (int j = 0; j < 4; ++j)
#pragma unroll
            for (int r = 0; r < 4; ++r) acc[i][j][r] = 0.f;

    auto issue = [&](int c, int s) {
        const int kcol = (c & 3) * 64;
        const __nv_bfloat16* asrc = (((c >> 2) == 1) ? a_lo : a_hi) + kcol;
        const __nv_bfloat16* bsrc = b_row + kcol + (((c >> 2) == 2) ? 256 : 0);
        const uint32_t sa = sbase + s * STG_BYTES;
        const uint32_t sb = sa + 16384;
#pragma unroll
        for (int i = 0; i < 4; ++i) {
            const int e = (lhalf * 4 + i) * 8;
            cp_async16(sa + sdst[i], asrc + e);
            cp_async16(sb + sdst[i], bsrc + e);
        }
        asm volatile("cp.async.commit_group;" ::: "memory");
    };

    issue(0, 0);
    issue(1, 1);

#pragma unroll 1
    for (int c = 0; c < 12; ++c) {
        if (c < 11) asm volatile("cp.async.wait_group 1;" ::: "memory");
        else        asm volatile("cp.async.wait_group 0;" ::: "memory");
        __syncthreads();
        if (c + 2 < 12) issue(c + 2, (c + 2) % 3);

        const uint32_t sa = sbase + (c % 3) * STG_BYTES;
        const uint32_t sb = sa + 16384;
#pragma unroll
        for (int ks = 0; ks < 4; ++ks) {
            uint32_t afr[4][4], bfr[4][2];
#pragma unroll
            for (int mf = 0; mf < 4; ++mf) {
                const int r = rA[mf];
                ldm_x4(afr[mf], sa + (uint32_t)((r * 8 + ((ks * 2 + mhi) ^ (r & 7))) * 16));
            }
#pragma unroll
            for (int q = 0; q < 4; ++q) {
                const int r = rB[q];
                ldm_x2(bfr[q], sb + (uint32_t)((r * 8 + ((ks * 2 + mB) ^ (r & 7))) * 16));
            }
#pragma unroll
            for (int mf = 0; mf < 4; ++mf)
#pragma unroll
                for (int q = 0; q < 4; ++q)
                    mma_bf16(acc[mf][q], afr[mf], bfr[q]);
        }
    }

    // epilogue: + biasp -> Cout
    const int mrow = m0 + wm * 64 + (lane >> 2);
    const int nco  = n0 + wn * 32 + (lane & 3) * 2;
#pragma unroll
    for (int q = 0; q < 4; ++q) {
        const float bp0 = g_biasp[nco + q * 8];
        const float bp1 = g_biasp[nco + q * 8 + 1];
#pragma unroll
        for (int mf = 0; mf < 4; ++mf) {
            const int m = mrow + mf * 16;
            float2 v0 = make_float2(acc[mf][q][0] + bp0, acc[mf][q][1] + bp1);
            float2 v1 = make_float2(acc[mf][q][2] + bp0, acc[mf][q][3] + bp1);
            *(float2*)&Cout[(size_t)m * G4 + nco + q * 8] = v0;
            *(float2*)&Cout[(size_t)(m + 8) * G4 + nco + q * 8] = v1;
        }
    }
}

// ---------------- persistent LSTM recurrence --------------------------------
// One launch for all 64 steps. 128 CTAs (16 M x 8 N), CTA tile 64x128.
// Whh (permuted, hi|lo) resident in smem (128KB); h streamed via 3-stage ring.
// Gate permutation: tile n-cols = q*32+j -> all 4 gates of hidden j in-thread.
#define PS_B_BYTES 131072
#define PS_A_STG   8192
#define PS_SMEM    (PS_B_BYTES + 3 * PS_A_STG)

__global__ __launch_bounds__(256)
void lstm_persist_kernel(float* __restrict__ out)
{
    extern __shared__ __align__(1024) char smem[];
    const uint32_t sbB = smem_u32(smem);
    const uint32_t sbA = sbB + PS_B_BYTES;
    const int t = threadIdx.x;
    const int lane = t & 31;
    const int wid = t >> 5;
    const int wm = wid >> 2;           // 0..1 (32 rows each)
    const int wn = wid & 3;            // 0..3
    const int mb = blockIdx.x & 15;
    const int nb = blockIdx.x >> 4;
    const int m0 = mb * 64;
    const int n0 = nb * 128;

    // ---- load resident B (Whh permuted rows n0..n0+128, 512 cols hi|lo) ----
    for (int ug = t; ug < 8192; ug += 256) {
        const int r = ug >> 6, u = ug & 63;
        cp_async16(sbB + (uint32_t)((r * 64 + (u & ~7) + ((u & 7) ^ (r & 7))) * 16),
                   g_whh + (size_t)(n0 + r) * 512 + u * 8);
    }
    asm volatile("cp.async.commit_group;" ::: "memory");
    asm volatile("cp.async.wait_group 0;" ::: "memory");
    __syncthreads();

    const int mhi = lane >> 4;
    const int mB  = (lane >> 3) & 1;
    int rA[2], rB[4];
#pragma unroll
    for (int mf = 0; mf < 2; ++mf)
        rA[mf] = wm * 32 + mf * 16 + ((lane >> 3) & 1) * 8 + (lane & 7);
#pragma unroll
    for (int q = 0; q < 4; ++q)
        rB[q] = q * 32 + wn * 8 + (lane & 7);

    const int jl0 = wn * 8 + (lane & 3) * 2;
    const int hcol = nb * 32;

#pragma unroll 1
    for (int ts = 0; ts < TSTEPS; ++ts) {
        const __nv_bfloat16* hhi_r = g_hhi[ts & 1];
        const __nv_bfloat16* hlo_r = g_hlo[ts & 1];
        __nv_bfloat16* hhi_w = g_hhi[(ts & 1) ^ 1];
        __nv_bfloat16* hlo_w = g_hlo[(ts & 1) ^ 1];
        const float* xg_t = g_xg + (size_t)ts * BATCH * G4;
        float* out_t = out + (size_t)ts * BATCH * HDIM;

        float acc[2][4][4];
#pragma unroll
        for (int i = 0; i < 2; ++i)
#pragma unroll
            for (int j = 0; j < 4; ++j)
#pragma unroll
                for (int r = 0; r < 4; ++r) acc[i][j][r] = 0.f;

        auto issueA = [&](int c, int s) {
            const int term = c >> 2, kc = c & 3;
            const __nv_bfloat16* hsrc = (term == 1) ? hlo_r : hhi_r;
            const uint32_t sa = sbA + s * PS_A_STG;
#pragma unroll
            for (int i = 0; i < 2; ++i) {
                const int ug = t + i * 256;
                const int r = ug >> 3, w = ug & 7;
                cp_async16(sa + (uint32_t)((r * 8 + (w ^ (r & 7))) * 16),
                           hsrc + (size_t)(m0 + r) * HDIM + kc * 64 + w * 8);
            }
            asm volatile("cp.async.commit_group;" ::: "memory");
        };

        issueA(0, 0);
        issueA(1, 1);

#pragma unroll 1
        for (int c = 0; c < 12; ++c) {
            if (c < 11) asm volatile("cp.async.wait_group 1;" ::: "memory");
            else        asm volatile("cp.async.wait_group 0;" ::: "memory");
            __syncthreads();
            if (c + 2 < 12) issueA(c + 2, (c + 2) % 3);

            const uint32_t sa = sbA + (c % 3) * PS_A_STG;
            const int kc8 = ((c & 3) + (((c >> 2) == 2) ? 4 : 0)) * 8;
#pragma unroll
            for (int ks = 0; ks < 4; ++ks) {
                uint32_t afr[2][4], bfr[4][2];
#pragma unroll
                for (int mf = 0; mf < 2; ++mf) {
                    const int r = rA[mf];
                    ldm_x4(afr[mf], sa + (uint32_t)((r * 8 + ((ks * 2 + mhi) ^ (r & 7))) * 16));
                }
#pragma unroll
                for (int q = 0; q < 4; ++q) {
                    const int r = rB[q];
                    ldm_x2(bfr[q], sbB + (uint32_t)((r * 64 + kc8 + ((ks * 2 + mB) ^ (r & 7))) * 16));
                }
#pragma unroll
                for (int mf = 0; mf < 2; ++mf)
#pragma unroll
                    for (int q = 0; q < 4; ++q)
                        mma_bf16(acc[mf][q], afr[mf], bfr[q]);
            }
        }

        // ---- fused LSTM cell epilogue ----
#pragma unroll
        for (int mf = 0; mf < 2; ++mf) {
#pragma unroll
            for (int h = 0; h < 2; ++h) {
                const int m = m0 + wm * 32 + mf * 16 + (lane >> 2) + h * 8;
                const float* xr = xg_t + (size_t)m * G4 + n0;
#pragma unroll
                for (int jj = 0; jj < 2; ++jj) {
                    const int jl = jl0 + jj;
                    const int rsel = h * 2 + jj;
                    const float gi = acc[mf][0][rsel] + xr[jl];
                    const float gf = acc[mf][1][rsel] + xr[32 + jl];
                    const float gg = acc[mf][2][rsel] + xr[64 + jl];
                    const float go = acc[mf][3][rsel] + xr[96 + jl];
                    const float iv = 1.f / (1.f + expf(-gi));
                    const float fv = 1.f / (1.f + expf(-gf));
                    const float gv = tanhf(gg);
                    const float ov = 1.f / (1.f + expf(-go));
                    const int idx = m * HDIM + hcol + jl;
                    const float cn = fv * g_c[idx] + iv * gv;
                    const float hn = ov * tanhf(cn);
                    g_c[idx] = cn;
                    const __nv_bfloat16 hh = __float2bfloat16(hn);
                    hhi_w[idx] = hh;
                    hlo_w[idx] = __float2bfloat16(hn - __bfloat162float(hh));
                    out_t[idx] = hn + g_img[idx];
                }
            }
        }

        if (ts != TSTEPS - 1) grid_barrier();
    }
}

// ---------------- all prepacking in ONE kernel -------------------------------
// seg0 emb split | seg1 Wih pack | seg2 Whh pack | seg3 init h/c | seg4 biasp
#define S_EMB  ((size_t)VOCAB * HDIM)        // 8,192,000
#define S_W    ((size_t)G4 * HDIM)           // 262,144
#define S_HC   ((size_t)BATCH * HDIM)        // 262,144
#define PREP_TOTAL (S_EMB + 2 * S_W + S_HC + G4)

__global__ void prep_all_kernel(const float* __restrict__ emb,
                                const float* __restrict__ Wih,
                                const float* __restrict__ Whh,
                                const float* __restrict__ bih,
                                const float* __restrict__ bhh)
{
    const size_t i = (size_t)blockIdx.x * 256 + threadIdx.x;
    if (i < S_EMB) {
        const float v = emb[i];
        const __nv_bfloat16 h = __float2bfloat16(v);
        g_ehi[i] = h;
        g_elo[i] = __float2bfloat16(v - __bfloat162float(h));
    } else if (i < S_EMB + 2 * S_W) {
        const size_t ii = i - S_EMB;
        const int which = (int)(ii / S_W);
        const int idx = (int)(ii % S_W);
        const int p = idx >> 8, k = idx & 255;
        const int nt = p >> 7, q = (p >> 5) & 3, j = p & 31;
        const int orig = q * 256 + nt * 32 + j;
        const float* W = which ? Whh : Wih;
        __nv_bfloat16* Wd = which ? g_whh : g_wih;
        const float v = W[orig * 256 + k];
        const __nv_bfloat16 h = __float2bfloat16(v);
        Wd[p * 512 + k] = h;
        Wd[p * 512 + 256 + k] = __float2bfloat16(v - __bfloat162float(h));
    } else if (i < S_EMB + 2 * S_W + S_HC) {
        const int idx = (int)(i - S_EMB - 2 * S_W);
        g_c[idx] = 0.f;
        g_hhi[0][idx] = __float2bfloat16(0.f);
        g_hlo[0][idx] = __float2bfloat16(0.f);
    } else if (i < PREP_TOTAL) {
        const int p = (int)(i - S_EMB - 2 * S_W - S_HC);
        const int nt = p >> 7, q = (p >> 5) & 3, j = p & 31;
        const int orig = q * 256 + nt * 32 + j;
        g_biasp[p] = bih[orig] + bhh[orig];
    }
}

// ---------------- fp32 image GEMM (small) ------------------------------------
__global__ __launch_bounds__(256)
void img_gemm_kernel(const float* __restrict__ A, const float* __restrict__ Bm,
                     float* __restrict__ C, const float* __restrict__ bias)
{
    const int N = HDIM, K = IMGD;
    __shared__ float As[16][64];
    __shared__ float Bs[16][64];
    const int tid = threadIdx.x;
    const int tx = tid & 15, ty = tid >> 4;
    const int m0 = blockIdx.x * 64, n0 = blockIdx.y * 64;
    const int lrow = tid >> 2, lcol4 = (tid & 3) * 4;
    const float* aptr = A + (size_t)(m0 + lrow) * K;
    const float* bptr = Bm + (size_t)(n0 + lrow) * K;
    float acc[4][4];
#pragma unroll
    for (int i = 0; i < 4; i++)
#pragma unroll
        for (int j = 0; j < 4; j++) acc[i][j] = 0.f;
    for (int k0 = 0; k0 < K; k0 += 16) {
        float4 av = *(const float4*)(aptr + k0 + lcol4);
        float4 bv = *(const float4*)(bptr + k0 + lcol4);
        As[lcol4 + 0][lrow] = av.x; As[lcol4 + 1][lrow] = av.y;
        As[lcol4 + 2][lrow] = av.z; As[lcol4 + 3][lrow] = av.w;
        Bs[lcol4 + 0][lrow] = bv.x; Bs[lcol4 + 1][lrow] = bv.y;
        Bs[lcol4 + 2][lrow] = bv.z; Bs[lcol4 + 3][lrow] = bv.w;
        __syncthreads();
#pragma unroll
        for (int k = 0; k < 16; k++) {
            float a[4], b[4];
            *(float4*)a = *(const float4*)&As[k][ty * 4];
            *(float4*)b = *(const float4*)&Bs[k][tx * 4];
#pragma unroll
            for (int i = 0; i < 4; i++)
#pragma unroll
                for (int j = 0; j < 4; j++) acc[i][j] = fmaf(a[i], b[j], acc[i][j]);
        }
        __syncthreads();
    }
#pragma unroll
    for (int i = 0; i < 4; i++)
#pragma unroll
        for (int j = 0; j < 4; j++)
            C[(size_t)(m0 + ty * 4 + i) * N + n0 + tx * 4 + j] =
                fmaxf(acc[i][j] + bias[n0 + tx * 4 + j], 0.f);
}

// ---------------- launcher ---------------------------------------------------
extern "C" void kernel_launch(void* const* d_in, const int* in_sizes, int n_in,
                              void* d_out, int out_size)
{
    const float* img  = (const float*)d_in[0];
    const int*   cap  = (const int*)  d_in[1];
    const float* Wimg = (const float*)d_in[2];
    const float* bimg = (const float*)d_in[3];
    const float* emb  = (const float*)d_in[4];
    const float* Wih  = (const float*)d_in[5];
    const float* Whh  = (const float*)d_in[6];
    const float* bih  = (const float*)d_in[7];
    const float* bhh  = (const float*)d_in[8];
    float* out = (float*)d_out;

    float* p_img; cudaGetSymbolAddress((void**)&p_img, g_img);
    float* p_xg;  cudaGetSymbolAddress((void**)&p_xg,  g_xg);

    cudaFuncSetAttribute(xg_mma_kernel, cudaFuncAttributeMaxDynamicSharedMemorySize, XG_SMEM);
    cudaFuncSetAttribute(lstm_persist_kernel, cudaFuncAttributeMaxDynamicSharedMemorySize, PS_SMEM);

    // 1: all prepacking + state init
    prep_all_kernel<<<(int)(PREP_TOTAL / 256), 256>>>(emb, Wih, Whh, bih, bhh);

    // 2: image branch (fp32)
    {
        dim3 grid(BATCH / 64, HDIM / 64);
        img_gemm_kernel<<<grid, 256>>>(img, Wimg, p_img, bimg);
    }

    // 3: xg = emb[cap] @ Wih'^T + biasp (permuted cols)
    {
        dim3 grid((TSTEPS * BATCH) / 128, G4 / 128);
        xg_mma_kernel<<<grid, 256, XG_SMEM>>>(cap, p_xg);
    }

    // 4: persistent recurrence (all 64 steps in one launch)
    lstm_persist_kernel<<<128, 256, PS_SMEM>>>(out);
}

// round 7
// speedup vs baseline: 4.2214x; 1.5400x over previous
#include <cuda_runtime.h>
#include <cuda_bf16.h>
#include <math.h>
#include <stdint.h>

#define HDIM   256
#define BATCH  1024
#define TSTEPS 64
#define IMGD   2048
#define G4     1024
#define VOCAB  32000

// ---------------- device scratch (no allocation allowed) -------------------
__device__ float g_img[BATCH * HDIM];
__device__ float g_xg[(size_t)TSTEPS * BATCH * G4];          // permuted gate cols
__device__ __nv_bfloat16 g_ehi[(size_t)VOCAB * HDIM];
__device__ __nv_bfloat16 g_elo[(size_t)VOCAB * HDIM];
__device__ __nv_bfloat16 g_wih[G4 * 2 * HDIM];               // [p][0:256]=hi, [256:512]=lo
__device__ __nv_bfloat16 g_whh[G4 * 2 * HDIM];
__device__ float g_biasp[G4];
__device__ __nv_bfloat16 g_hhi[2][BATCH * HDIM];
__device__ __nv_bfloat16 g_hlo[2][BATCH * HDIM];

// grid-barrier state (zero-initialized; count returns to 0 after each use)
__device__ int g_bar_count;
__device__ volatile unsigned g_bar_gen;

// ---------------- helpers ---------------------------------------------------
__device__ __forceinline__ uint32_t smem_u32(const void* p) {
    uint32_t a;
    asm("{ .reg .u64 t; cvta.to.shared.u64 t, %1; cvt.u32.u64 %0, t; }" : "=r"(a) : "l"(p));
    return a;
}
__device__ __forceinline__ void cp_async16(uint32_t saddr, const void* gaddr) {
    asm volatile("cp.async.cg.shared.global [%0], [%1], 16;" :: "r"(saddr), "l"(gaddr));
}
__device__ __forceinline__ void ldm_x4(uint32_t* r, uint32_t addr) {
    asm volatile("ldmatrix.sync.aligned.m8n8.x4.shared.b16 {%0,%1,%2,%3}, [%4];"
                 : "=r"(r[0]), "=r"(r[1]), "=r"(r[2]), "=r"(r[3]) : "r"(addr));
}
__device__ __forceinline__ void ldm_x2(uint32_t* r, uint32_t addr) {
    asm volatile("ldmatrix.sync.aligned.m8n8.x2.shared.b16 {%0,%1}, [%2];"
                 : "=r"(r[0]), "=r"(r[1]) : "r"(addr));
}
__device__ __forceinline__ void mma_bf16(float* d, const uint32_t* a, const uint32_t* b) {
    asm volatile("mma.sync.aligned.m16n8k16.row.col.f32.bf16.bf16.f32 "
                 "{%0,%1,%2,%3}, {%4,%5,%6,%7}, {%8,%9}, {%0,%1,%2,%3};"
                 : "+f"(d[0]), "+f"(d[1]), "+f"(d[2]), "+f"(d[3])
                 : "r"(a[0]), "r"(a[1]), "r"(a[2]), "r"(a[3]), "r"(b[0]), "r"(b[1]));
}

// proven R5 grid barrier: fence-by-all at entry, generation + nanosleep spin
__device__ __forceinline__ void grid_barrier() {
    __threadfence();
    __syncthreads();
    if (threadIdx.x == 0) {
        unsigned gen = g_bar_gen;
        if (atomicAdd(&g_bar_count, 1) == (int)gridDim.x - 1) {
            g_bar_count = 0;
            __threadfence();
            g_bar_gen = gen + 1;
        } else {
            while (g_bar_gen == gen) __nanosleep(32);
        }
        __threadfence();
    }
    __syncthreads();
}

// ---------------- xg GEMM: bf16-split tensor-core (validated R5) ------------
#define STG_BYTES 32768
#define XG_SMEM   (3 * STG_BYTES)

__global__ __launch_bounds__(256)
void xg_mma_kernel(const int* __restrict__ gather, float* __restrict__ Cout)
{
    extern __shared__ __align__(1024) char smem[];
    const uint32_t sbase = smem_u32(smem);
    const int t = threadIdx.x;
    const int lane = t & 31;
    const int wid = t >> 5;
    const int wm = wid >> 2;
    const int wn = wid & 3;
    const int m0 = blockIdx.x * 128;
    const int n0 = blockIdx.y * 128;

    const int lr = t >> 1;
    const int lhalf = t & 1;
    const int arow = gather[m0 + lr];
    const __nv_bfloat16* a_hi = g_ehi + (size_t)arow * HDIM;
    const __nv_bfloat16* a_lo = g_elo + (size_t)arow * HDIM;
    const __nv_bfloat16* b_row = g_wih + (size_t)(n0 + lr) * (2 * HDIM);

    uint32_t sdst[4];
#pragma unroll
    for (int i = 0; i < 4; ++i) {
        const int w = lhalf * 4 + i;
        sdst[i] = (uint32_t)((lr * 8 + (w ^ (lr & 7))) * 16);
    }

    int rA[4], rB[4];
    const int mhi = lane >> 4;
    const int mB  = (lane >> 3) & 1;
#pragma unroll
    for (int mf = 0; mf < 4; ++mf)
        rA[mf] = wm * 64 + mf * 16 + ((lane >> 3) & 1) * 8 + (lane & 7);
#pragma unroll
    for (int q = 0; q < 4; ++q)
        rB[q] = wn * 32 + q * 8 + (lane & 7);

    float acc[4][4][4];
#pragma unroll
    for (int i = 0; i < 4; ++i)
#pragma unroll
        for (int j = 0; j < 4; ++j)
#pragma unroll
            for (int r = 0; r < 4; ++r) acc[i][j][r] = 0.f;

    auto issue = [&](int c, int s) {
        const int kcol = (c & 3) * 64;
        const __nv_bfloat16* asrc = (((c >> 2) == 1) ? a_lo : a_hi) + kcol;
        const __nv_bfloat16* bsrc = b_row + kcol + (((c >> 2) == 2) ? 256 : 0);
        const uint32_t sa = sbase + s * STG_BYTES;
        const uint32_t sb = sa + 16384;
#pragma unroll
        for (int i = 0; i < 4; ++i) {
            const int e = (lhalf * 4 + i) * 8;
            cp_async16(sa + sdst[i], asrc + e);
            cp_async16(sb + sdst[i], bsrc + e);
        }
        asm volatile("cp.async.commit_group;" ::: "memory");
    };

    issue(0, 0);
    issue(1, 1);

#pragma unroll 1
    for (int c = 0; c < 12; ++c) {
        if (c < 11) asm volatile("cp.async.wait_group 1;" ::: "memory");
        else        asm volatile("cp.async.wait_group 0;" ::: "memory");
        __syncthreads();
        if (c + 2 < 12) issue(c + 2, (c + 2) % 3);

        const uint32_t sa = sbase + (c % 3) * STG_BYTES;
        const uint32_t sb = sa + 16384;
#pragma unroll
        for (int ks = 0; ks < 4; ++ks) {
            uint32_t afr[4][4], bfr[4][2];
#pragma unroll
            for (int mf = 0; mf < 4; ++mf) {
                const int r = rA[mf];
                ldm_x4(afr[mf], sa + (uint32_t)((r * 8 + ((ks * 2 + mhi) ^ (r & 7))) * 16));
            }
#pragma unroll
            for (int q = 0; q < 4; ++q) {
                const int r = rB[q];
                ldm_x2(bfr[q], sb + (uint32_t)((r * 8 + ((ks * 2 + mB) ^ (r & 7))) * 16));
            }
#pragma unroll
            for (int mf = 0; mf < 4; ++mf)
#pragma unroll
                for (int q = 0; q < 4; ++q)
                    mma_bf16(acc[mf][q], afr[mf], bfr[q]);
        }
    }

    const int mrow = m0 + wm * 64 + (lane >> 2);
    const int nco  = n0 + wn * 32 + (lane & 3) * 2;
#pragma unroll
    for (int q = 0; q < 4; ++q) {
        const float bp0 = g_biasp[nco + q * 8];
        const float bp1 = g_biasp[nco + q * 8 + 1];
#pragma unroll
        for (int mf = 0; mf < 4; ++mf) {
            const int m = mrow + mf * 16;
            float2 v0 = make_float2(acc[mf][q][0] + bp0, acc[mf][q][1] + bp1);
            float2 v1 = make_float2(acc[mf][q][2] + bp0, acc[mf][q][3] + bp1);
            *(float2*)&Cout[(size_t)m * G4 + nco + q * 8] = v0;
            *(float2*)&Cout[(size_t)(m + 8) * G4 + nco + q * 8] = v1;
        }
    }
}

// ---------------- persistent LSTM recurrence v3 -----------------------------
// 128 CTAs (16 mb x 8 nb), CTA tile 64x128(gate cols), 256 threads.
// Whh resident (128KB); whole h tile (64KB) loaded per step -> sync-free MMA
// loop; c and img in registers across all 64 steps; xg prefetched to smem.
// Full-grid barrier (proven R5 primitive) between steps.
#define PB_BYTES 131072
#define PA_BYTES 65536
#define PX_BYTES 33792               // 64 rows * 132 floats (padded)
#define PS_SMEM  (PB_BYTES + PA_BYTES + PX_BYTES)

__global__ __launch_bounds__(256)
void lstm_persist_kernel(float* __restrict__ out)
{
    extern __shared__ __align__(1024) char smem[];
    const uint32_t sbB = smem_u32(smem);
    const uint32_t sbA = sbB + PB_BYTES;
    const uint32_t sbX = sbA + PA_BYTES;
    float* sx = (float*)(smem + PB_BYTES + PA_BYTES);

    const int t = threadIdx.x;
    const int lane = t & 31;
    const int wid = t >> 5;
    const int wm = wid >> 2;           // 0..1 (32 rows)
    const int wn = wid & 3;            // 0..3
    const int mb = blockIdx.x & 15;
    const int nb = blockIdx.x >> 4;
    const int m0 = mb * 64;
    const int n0 = nb * 128;
    const int hcol = nb * 32;

    // ---- resident B: Whh permuted rows n0..n0+128, 512 cols (hi|lo) ----
    for (int ug = t; ug < 8192; ug += 256) {
        const int r = ug >> 6, u = ug & 63;
        cp_async16(sbB + (uint32_t)((r * 64 + (u & ~7) + ((u & 7) ^ (r & 7))) * 16),
                   g_whh + (size_t)(n0 + r) * 512 + u * 8);
    }
    asm volatile("cp.async.commit_group;" ::: "memory");
    asm volatile("cp.async.wait_group 0;" ::: "memory");
    __syncthreads();

    const int mhi = lane >> 4;
    const int mB  = (lane >> 3) & 1;
    int rA[2], rB[4];
#pragma unroll
    for (int mf = 0; mf < 2; ++mf)
        rA[mf] = wm * 32 + mf * 16 + ((lane >> 3) & 1) * 8 + (lane & 7);
#pragma unroll
    for (int q = 0; q < 4; ++q)
        rB[q] = q * 32 + wn * 8 + (lane & 7);

    const int jl0 = wn * 8 + (lane & 3) * 2;

    // ---- per-thread persistent state: c and img (8 cells each) ----
    float creg[2][2][2];
    float img_r[2][2][2];
#pragma unroll
    for (int mf = 0; mf < 2; ++mf)
#pragma unroll
        for (int h = 0; h < 2; ++h) {
            const int m = m0 + wm * 32 + mf * 16 + (lane >> 2) + h * 8;
            creg[mf][h][0] = 0.f; creg[mf][h][1] = 0.f;
            img_r[mf][h][0] = g_img[m * HDIM + hcol + jl0];
            img_r[mf][h][1] = g_img[m * HDIM + hcol + jl0 + 1];
        }

#pragma unroll 1
    for (int ts = 0; ts < TSTEPS; ++ts) {
        const __nv_bfloat16* hhi_r = g_hhi[ts & 1];
        const __nv_bfloat16* hlo_r = g_hlo[ts & 1];
        __nv_bfloat16* hhi_w = g_hhi[(ts & 1) ^ 1];
        __nv_bfloat16* hlo_w = g_hlo[(ts & 1) ^ 1];
        const float* xg_t = g_xg + (size_t)ts * BATCH * G4;
        float* out_t = out + (size_t)ts * BATCH * HDIM;

        if (ts) grid_barrier();

        // ---- load whole A (h hi+lo, 64x256) : group 0 ----
#pragma unroll
        for (int i = 0; i < 16; ++i) {
            const int ug = i * 256 + t;
            const int buf = ug >> 11;
            const int idx = ug & 2047;
            const int r = idx >> 5, u = idx & 31;
            const __nv_bfloat16* src = (buf ? hlo_r : hhi_r) + (size_t)(m0 + r) * HDIM + u * 8;
            cp_async16(sbA + (uint32_t)(buf * 32768 + (r * 32 + (u & ~7) + ((u & 7) ^ (r & 7))) * 16), src);
        }
        asm volatile("cp.async.commit_group;" ::: "memory");

        // ---- prefetch xg tile (64x128 fp32, padded stride 132) : group 1 ----
#pragma unroll
        for (int i = 0; i < 8; ++i) {
            const int ug = i * 256 + t;
            const int r = ug >> 5, w = ug & 31;
            cp_async16(sbX + (uint32_t)(r * 528 + w * 16),
                       xg_t + (size_t)(m0 + r) * G4 + n0 + w * 4);
        }
        asm volatile("cp.async.commit_group;" ::: "memory");

        asm volatile("cp.async.wait_group 1;" ::: "memory");
        __syncthreads();

        float acc[2][4][4];
#pragma unroll
        for (int i = 0; i < 2; ++i)
#pragma unroll
            for (int j = 0; j < 4; ++j)
#pragma unroll
                for (int r = 0; r < 4; ++r) acc[i][j][r] = 0.f;

        // ---- sync-free MMA loop: shared fragments across the 3 split terms ----
#pragma unroll 1
        for (int kc = 0; kc < 4; ++kc) {
#pragma unroll
            for (int ks = 0; ks < 4; ++ks) {
                uint32_t ahi[2][4], alo[2][4], bhi[4][2], blo[4][2];
#pragma unroll
                for (int mf = 0; mf < 2; ++mf) {
                    const int r = rA[mf];
                    const uint32_t aoff = (uint32_t)((r * 32 + kc * 8 + ((ks * 2 + mhi) ^ (r & 7))) * 16);
                    ldm_x4(ahi[mf], sbA + aoff);
                    ldm_x4(alo[mf], sbA + 32768 + aoff);
                }
#pragma unroll
                for (int q = 0; q < 4; ++q) {
                    const int r = rB[q];
                    const uint32_t sw = (uint32_t)(((ks * 2 + mB) ^ (r & 7)) * 16);
                    ldm_x2(bhi[q], sbB + (uint32_t)((r * 64 + kc * 8) * 16) + sw);
                    ldm_x2(blo[q], sbB + (uint32_t)((r * 64 + 32 + kc * 8) * 16) + sw);
                }
#pragma unroll
                for (int mf = 0; mf < 2; ++mf)
#pragma unroll
                    for (int q = 0; q < 4; ++q) {
                        mma_bf16(acc[mf][q], ahi[mf], bhi[q]);
                        mma_bf16(acc[mf][q], alo[mf], bhi[q]);
                        mma_bf16(acc[mf][q], ahi[mf], blo[q]);
                    }
            }
        }

        asm volatile("cp.async.wait_group 0;" ::: "memory");
        __syncthreads();

        // ---- fused LSTM cell epilogue (c in regs, xg from smem) ----
#pragma unroll
        for (int mf = 0; mf < 2; ++mf) {
#pragma unroll
            for (int h = 0; h < 2; ++h) {
                const int m = m0 + wm * 32 + mf * 16 + (lane >> 2) + h * 8;
                const int r = m - m0;
                const float* xr = sx + r * 132;
                float hn[2];
#pragma unroll
                for (int jj = 0; jj < 2; ++jj) {
                    const int jl = jl0 + jj;
                    const int rs = h * 2 + jj;
                    const float gi = acc[mf][0][rs] + xr[jl];
                    const float gf = acc[mf][1][rs] + xr[32 + jl];
                    const float gg = acc[mf][2][rs] + xr[64 + jl];
                    const float go = acc[mf][3][rs] + xr[96 + jl];
                    const float iv = 1.f / (1.f + expf(-gi));
                    const float fv = 1.f / (1.f + expf(-gf));
                    const float gv = tanhf(gg);
                    const float ov = 1.f / (1.f + expf(-go));
                    const float cn = fv * creg[mf][h][jj] + iv * gv;
                    hn[jj] = ov * tanhf(cn);
                    creg[mf][h][jj] = cn;
                }
                const int idx = m * HDIM + hcol + jl0;
                const __nv_bfloat16 h0 = __float2bfloat16(hn[0]);
                const __nv_bfloat16 h1 = __float2bfloat16(hn[1]);
                __nv_bfloat162 hhp; hhp.x = h0; hhp.y = h1;
                __nv_bfloat162 hlp;
                hlp.x = __float2bfloat16(hn[0] - __bfloat162float(h0));
                hlp.y = __float2bfloat16(hn[1] - __bfloat162float(h1));
                *(__nv_bfloat162*)&hhi_w[idx] = hhp;
                *(__nv_bfloat162*)&hlo_w[idx] = hlp;
                float2 ov2 = make_float2(hn[0] + img_r[mf][h][0], hn[1] + img_r[mf][h][1]);
                *(float2*)&out_t[idx] = ov2;
            }
        }
    }
}

// ---------------- all prepacking in ONE kernel -------------------------------
#define S_EMB  ((size_t)VOCAB * HDIM)
#define S_W    ((size_t)G4 * HDIM)
#define S_HC   ((size_t)BATCH * HDIM)
#define PREP_TOTAL (S_EMB + 2 * S_W + S_HC + G4)

__global__ void prep_all_kernel(const float* __restrict__ emb,
                                const float* __restrict__ Wih,
                                const float* __restrict__ Whh,
                                const float* __restrict__ bih,
                                const float* __restrict__ bhh)
{
    const size_t i = (size_t)blockIdx.x * 256 + threadIdx.x;
    if (i < S_EMB) {
        const float v = emb[i];
        const __nv_bfloat16 h = __float2bfloat16(v);
        g_ehi[i] = h;
        g_elo[i] = __float2bfloat16(v - __bfloat162float(h));
    } else if (i < S_EMB + 2 * S_W) {
        const size_t ii = i - S_EMB;
        const int which = (int)(ii / S_W);
        const int idx = (int)(ii % S_W);
        const int p = idx >> 8, k = idx & 255;
        const int nt = p >> 7, q = (p >> 5) & 3, j = p & 31;
        const int orig = q * 256 + nt * 32 + j;
        const float* W = which ? Whh : Wih;
        __nv_bfloat16* Wd = which ? g_whh : g_wih;
        const float v = W[orig * 256 + k];
        const __nv_bfloat16 h = __float2bfloat16(v);
        Wd[p * 512 + k] = h;
        Wd[p * 512 + 256 + k] = __float2bfloat16(v - __bfloat162float(h));
    } else if (i < S_EMB + 2 * S_W + S_HC) {
        const int idx = (int)(i - S_EMB - 2 * S_W);
        g_hhi[0][idx] = __float2bfloat16(0.f);
        g_hlo[0][idx] = __float2bfloat16(0.f);
    } else if (i < PREP_TOTAL) {
        const int p = (int)(i - S_EMB - 2 * S_W - S_HC);
        const int nt = p >> 7, q = (p >> 5) & 3, j = p & 31;
        const int orig = q * 256 + nt * 32 + j;
        g_biasp[p] = bih[orig] + bhh[orig];
    }
}

// ---------------- fp32 image GEMM (small) ------------------------------------
__global__ __launch_bounds__(256)
void img_gemm_kernel(const float* __restrict__ A, const float* __restrict__ Bm,
                     float* __restrict__ C, const float* __restrict__ bias)
{
    const int N = HDIM, K = IMGD;
    __shared__ float As[16][64];
    __shared__ float Bs[16][64];
    const int tid = threadIdx.x;
    const int tx = tid & 15, ty = tid >> 4;
    const int m0 = blockIdx.x * 64, n0 = blockIdx.y * 64;
    const int lrow = tid >> 2, lcol4 = (tid & 3) * 4;
    const float* aptr = A + (size_t)(m0 + lrow) * K;
    const float* bptr = Bm + (size_t)(n0 + lrow) * K;
    float acc[4][4];
#pragma unroll
    for (int i = 0; i < 4; i++)
#pragma unroll
        for (int j = 0; j < 4; j++) acc[i][j] = 0.f;
    for (int k0 = 0; k0 < K; k0 += 16) {
        float4 av = *(const float4*)(aptr + k0 + lcol4);
        float4 bv = *(const float4*)(bptr + k0 + lcol4);
        As[lcol4 + 0][lrow] = av.x; As[lcol4 + 1][lrow] = av.y;
        As[lcol4 + 2][lrow] = av.z; As[lcol4 + 3][lrow] = av.w;
        Bs[lcol4 + 0][lrow] = bv.x; Bs[lcol4 + 1][lrow] = bv.y;
        Bs[lcol4 + 2][lrow] = bv.z; Bs[lcol4 + 3][lrow] = bv.w;
        __syncthreads();
#pragma unroll
        for (int k = 0; k < 16; k++) {
            float a[4], b[4];
            *(float4*)a = *(const float4*)&As[k][ty * 4];
            *(float4*)b = *(const float4*)&Bs[k][tx * 4];
#pragma unroll
            for (int i = 0; i < 4; i++)
#pragma unroll
                for (int j = 0; j < 4; j++) acc[i][j] = fmaf(a[i], b[j], acc[i][j]);
        }
        __syncthreads();
    }
#pragma unroll
    for (int i = 0; i < 4; i++)
#pragma unroll
        for (int j = 0; j < 4; j++)
            C[(size_t)(m0 + ty * 4 + i) * N + n0 + tx * 4 + j] =
                fmaxf(acc[i][j] + bias[n0 + tx * 4 + j], 0.f);
}

// ---------------- launcher ---------------------------------------------------
extern "C" void kernel_launch(void* const* d_in, const int* in_sizes, int n_in,
                              void* d_out, int out_size)
{
    const float* img  = (const float*)d_in[0];
    const int*   cap  = (const int*)  d_in[1];
    const float* Wimg = (const float*)d_in[2];
    const float* bimg = (const float*)d_in[3];
    const float* emb  = (const float*)d_in[4];
    const float* Wih  = (const float*)d_in[5];
    const float* Whh  = (const float*)d_in[6];
    const float* bih  = (const float*)d_in[7];
    const float* bhh  = (const float*)d_in[8];
    float* out = (float*)d_out;

    float* p_img; cudaGetSymbolAddress((void**)&p_img, g_img);
    float* p_xg;  cudaGetSymbolAddress((void**)&p_xg,  g_xg);

    cudaFuncSetAttribute(xg_mma_kernel, cudaFuncAttributeMaxDynamicSharedMemorySize, XG_SMEM);
    cudaFuncSetAttribute(lstm_persist_kernel, cudaFuncAttributeMaxDynamicSharedMemorySize, PS_SMEM);

    prep_all_kernel<<<(int)((PREP_TOTAL + 255) / 256), 256>>>(emb, Wih, Whh, bih, bhh);

    {
        dim3 grid(BATCH / 64, HDIM / 64);
        img_gemm_kernel<<<grid, 256>>>(img, Wimg, p_img, bimg);
    }

    {
        dim3 grid((TSTEPS * BATCH) / 128, G4 / 128);
        xg_mma_kernel<<<grid, 256, XG_SMEM>>>(cap, p_xg);
    }

    lstm_persist_kernel<<<128, 256, PS_SMEM>>>(out);
}

// round 8
// speedup vs baseline: 4.8619x; 1.1517x over previous
#include <cuda_runtime.h>
#include <cuda_bf16.h>
#include <math.h>
#include <stdint.h>

#define HDIM   256
#define BATCH  1024
#define TSTEPS 64
#define IMGD   2048
#define G4     1024
#define VOCAB  32000

// ---------------- device scratch (no allocation allowed) -------------------
__device__ float g_img[BATCH * HDIM];
__device__ float g_proj[(size_t)VOCAB * G4];                 // vocab projection (131MB)
__device__ __nv_bfloat16 g_ehi[(size_t)VOCAB * HDIM];
__device__ __nv_bfloat16 g_elo[(size_t)VOCAB * HDIM];
__device__ __nv_bfloat16 g_wih[G4 * 2 * HDIM];               // [p][0:256]=hi, [256:512]=lo
__device__ __nv_bfloat16 g_whh[G4 * 2 * HDIM];
__device__ float g_biasp[G4];
__device__ __nv_bfloat16 g_hhi[2][BATCH * HDIM];
__device__ __nv_bfloat16 g_hlo[2][BATCH * HDIM];

// grid-barrier state
__device__ int g_bar_count;
__device__ volatile unsigned g_bar_gen;

// ---------------- helpers ---------------------------------------------------
__device__ __forceinline__ uint32_t smem_u32(const void* p) {
    uint32_t a;
    asm("{ .reg .u64 t; cvta.to.shared.u64 t, %1; cvt.u32.u64 %0, t; }" : "=r"(a) : "l"(p));
    return a;
}
__device__ __forceinline__ void cp_async16(uint32_t saddr, const void* gaddr) {
    asm volatile("cp.async.cg.shared.global [%0], [%1], 16;" :: "r"(saddr), "l"(gaddr));
}
__device__ __forceinline__ void ldm_x4(uint32_t* r, uint32_t addr) {
    asm volatile("ldmatrix.sync.aligned.m8n8.x4.shared.b16 {%0,%1,%2,%3}, [%4];"
                 : "=r"(r[0]), "=r"(r[1]), "=r"(r[2]), "=r"(r[3]) : "r"(addr));
}
__device__ __forceinline__ void ldm_x2(uint32_t* r, uint32_t addr) {
    asm volatile("ldmatrix.sync.aligned.m8n8.x2.shared.b16 {%0,%1}, [%2];"
                 : "=r"(r[0]), "=r"(r[1]) : "r"(addr));
}
__device__ __forceinline__ void mma_bf16(float* d, const uint32_t* a, const uint32_t* b) {
    asm volatile("mma.sync.aligned.m16n8k16.row.col.f32.bf16.bf16.f32 "
                 "{%0,%1,%2,%3}, {%4,%5,%6,%7}, {%8,%9}, {%0,%1,%2,%3};"
                 : "+f"(d[0]), "+f"(d[1]), "+f"(d[2]), "+f"(d[3])
                 : "r"(a[0]), "r"(a[1]), "r"(a[2]), "r"(a[3]), "r"(b[0]), "r"(b[1]));
}

// proven grid barrier
__device__ __forceinline__ void grid_barrier() {
    __threadfence();
    __syncthreads();
    if (threadIdx.x == 0) {
        unsigned gen = g_bar_gen;
        if (atomicAdd(&g_bar_count, 1) == (int)gridDim.x - 1) {
            g_bar_count = 0;
            __threadfence();
            g_bar_gen = gen + 1;
        } else {
            while (g_bar_gen == gen) __nanosleep(32);
        }
        __threadfence();
    }
    __syncthreads();
}

// ---------------- vocab-projection GEMM (bf16-split MMA) --------------------
// proj[32000,1024] = emb_all @ Wih'^T + biasp. CTA 128x128, 256 thr.
#define STG_BYTES 32768
#define XG_SMEM   (3 * STG_BYTES)

__global__ __launch_bounds__(256)
void proj_mma_kernel(float* __restrict__ Cout)
{
    extern __shared__ __align__(1024) char smem[];
    const uint32_t sbase = smem_u32(smem);
    const int t = threadIdx.x;
    const int lane = t & 31;
    const int wid = t >> 5;
    const int wm = wid >> 2;
    const int wn = wid & 3;
    const int m0 = blockIdx.x * 128;
    const int n0 = blockIdx.y * 128;

    const int lr = t >> 1;
    const int lhalf = t & 1;
    const __nv_bfloat16* a_hi = g_ehi + (size_t)(m0 + lr) * HDIM;
    const __nv_bfloat16* a_lo = g_elo + (size_t)(m0 + lr) * HDIM;
    const __nv_bfloat16* b_row = g_wih + (size_t)(n0 + lr) * (2 * HDIM);

    uint32_t sdst[4];
#pragma unroll
    for (int i = 0; i < 4; ++i) {
        const int w = lhalf * 4 + i;
        sdst[i] = (uint32_t)((lr * 8 + (w ^ (lr & 7))) * 16);
    }

    int rA[4], rB[4];
    const int mhi = lane >> 4;
    const int mB  = (lane >> 3) & 1;
#pragma unroll
    for (int mf = 0; mf < 4; ++mf)
        rA[mf] = wm * 64 + mf * 16 + ((lane >> 3) & 1) * 8 + (lane & 7);
#pragma unroll
    for (int q = 0; q < 4; ++q)
        rB[q] = wn * 32 + q * 8 + (lane & 7);

    float acc[4][4][4];
#pragma unroll
    for (int i = 0; i < 4; ++i)
#pragma unroll
        for (int j = 0; j < 4; ++j)
#pragma unroll
            for (int r = 0; r < 4; ++r) acc[i][j][r] = 0.f;

    auto issue = [&](int c, int s) {
        const int kcol = (c & 3) * 64;
        const __nv_bfloat16* asrc = (((c >> 2) == 1) ? a_lo : a_hi) + kcol;
        const __nv_bfloat16* bsrc = b_row + kcol + (((c >> 2) == 2) ? 256 : 0);
        const uint32_t sa = sbase + s * STG_BYTES;
        const uint32_t sb = sa + 16384;
#pragma unroll
        for (int i = 0; i < 4; ++i) {
            const int e = (lhalf * 4 + i) * 8;
            cp_async16(sa + sdst[i], asrc + e);
            cp_async16(sb + sdst[i], bsrc + e);
        }
        asm volatile("cp.async.commit_group;" ::: "memory");
    };

    issue(0, 0);
    issue(1, 1);

#pragma unroll 1
    for (int c = 0; c < 12; ++c) {
        if (c < 11) asm volatile("cp.async.wait_group 1;" ::: "memory");
        else        asm volatile("cp.async.wait_group 0;" ::: "memory");
        __syncthreads();
        if (c + 2 < 12) issue(c + 2, (c + 2) % 3);

        const uint32_t sa = sbase + (c % 3) * STG_BYTES;
        const uint32_t sb = sa + 16384;
#pragma unroll
        for (int ks = 0; ks < 4; ++ks) {
            uint32_t afr[4][4], bfr[4][2];
#pragma unroll
            for (int mf = 0; mf < 4; ++mf) {
                const int r = rA[mf];
                ldm_x4(afr[mf], sa + (uint32_t)((r * 8 + ((ks * 2 + mhi) ^ (r & 7))) * 16));
            }
#pragma unroll
            for (int q = 0; q < 4; ++q) {
                const int r = rB[q];
                ldm_x2(bfr[q], sb + (uint32_t)((r * 8 + ((ks * 2 + mB) ^ (r & 7))) * 16));
            }
#pragma unroll
            for (int mf = 0; mf < 4; ++mf)
#pragma unroll
                for (int q = 0; q < 4; ++q)
                    mma_bf16(acc[mf][q], afr[mf], bfr[q]);
        }
    }

    const int mrow = m0 + wm * 64 + (lane >> 2);
    const int nco  = n0 + wn * 32 + (lane & 3) * 2;
#pragma unroll
    for (int q = 0; q < 4; ++q) {
        const float bp0 = g_biasp[nco + q * 8];
        const float bp1 = g_biasp[nco + q * 8 + 1];
#pragma unroll
        for (int mf = 0; mf < 4; ++mf) {
            const int m = mrow + mf * 16;
            float2 v0 = make_float2(acc[mf][q][0] + bp0, acc[mf][q][1] + bp1);
            float2 v1 = make_float2(acc[mf][q][2] + bp0, acc[mf][q][3] + bp1);
            *(float2*)&Cout[(size_t)m * G4 + nco + q * 8] = v0;
            *(float2*)&Cout[(size_t)(m + 8) * G4 + nco + q * 8] = v1;
        }
    }
}

// ---------------- persistent LSTM recurrence v4 -----------------------------
// 128 CTAs (16 mb x 8 nb), tile 64x128, 512 threads (16 warps: 4 wm x 4 wn).
// Whh resident; h tile loaded per step; xg gathered from g_proj via cap and
// prefetched BEFORE the grid barrier; c/img in registers.
#define PB_BYTES 131072
#define PA_BYTES 65536
#define PX_BYTES 33792               // 64 rows * 132 floats (padded)
#define PS_SMEM  (PB_BYTES + PA_BYTES + PX_BYTES)

__global__ __launch_bounds__(512)
void lstm_persist_kernel(const int* __restrict__ cap, float* __restrict__ out)
{
    extern __shared__ __align__(1024) char smem[];
    const uint32_t sbB = smem_u32(smem);
    const uint32_t sbA = sbB + PB_BYTES;
    const uint32_t sbX = sbA + PA_BYTES;
    float* sx = (float*)(smem + PB_BYTES + PA_BYTES);

    const int t = threadIdx.x;
    const int lane = t & 31;
    const int wid = t >> 5;
    const int wm = wid >> 2;           // 0..3 (16 rows each)
    const int wn = wid & 3;            // 0..3
    const int mb = blockIdx.x & 15;
    const int nb = blockIdx.x >> 4;
    const int m0 = mb * 64;
    const int n0 = nb * 128;
    const int hcol = nb * 32;

    // ---- resident B: Whh permuted rows n0..n0+128, 512 cols (hi|lo) ----
#pragma unroll
    for (int i = 0; i < 16; ++i) {
        const int ug = i * 512 + t;
        const int r = ug >> 6, u = ug & 63;
        cp_async16(sbB + (uint32_t)((r * 64 + (u & ~7) + ((u & 7) ^ (r & 7))) * 16),
                   g_whh + (size_t)(n0 + r) * 512 + u * 8);
    }
    asm volatile("cp.async.commit_group;" ::: "memory");

    const int mhi = lane >> 4;
    const int mB  = (lane >> 3) & 1;
    const int rA = wm * 16 + ((lane >> 3) & 1) * 8 + (lane & 7);
    int rB[4];
#pragma unroll
    for (int q = 0; q < 4; ++q)
        rB[q] = q * 32 + wn * 8 + (lane & 7);

    const int jl0 = wn * 8 + (lane & 3) * 2;

    // ---- per-thread state: c (zeros) and img (4 cells) ----
    float creg[2][2];
    float img_r[2][2];
#pragma unroll
    for (int h = 0; h < 2; ++h) {
        const int m = m0 + wm * 16 + (lane >> 2) + h * 8;
        creg[h][0] = 0.f; creg[h][1] = 0.f;
        img_r[h][0] = g_img[m * HDIM + hcol + jl0];
        img_r[h][1] = g_img[m * HDIM + hcol + jl0 + 1];
    }

    // xg prefetch (gathered proj rows); X tile 64x128 fp32 padded to 132
    auto issueX = [&](int ts) {
        const int* capt = cap + ts * BATCH + m0;
#pragma unroll
        for (int i = 0; i < 4; ++i) {
            const int ug = i * 512 + t;
            const int r = ug >> 5, w = ug & 31;
            const int ci = __ldg(capt + r);
            cp_async16(sbX + (uint32_t)(r * 528 + w * 16),
                       g_proj + (size_t)ci * G4 + n0 + w * 4);
        }
        asm volatile("cp.async.commit_group;" ::: "memory");
    };

    issueX(0);   // overlaps with B load completing

    asm volatile("cp.async.wait_group 1;" ::: "memory");  // B resident (X may still fly)
    __syncthreads();

#pragma unroll 1
    for (int ts = 0; ts < TSTEPS; ++ts) {
        const __nv_bfloat16* hhi_r = g_hhi[ts & 1];
        const __nv_bfloat16* hlo_r = g_hlo[ts & 1];
        __nv_bfloat16* hhi_w = g_hhi[(ts & 1) ^ 1];
        __nv_bfloat16* hlo_w = g_hlo[(ts & 1) ^ 1];
        float* out_t = out + (size_t)ts * BATCH * HDIM;

        if (ts) grid_barrier();

        // ---- load whole A (h hi+lo, 64x256) ----
#pragma unroll
        for (int i = 0; i < 8; ++i) {
            const int ug = i * 512 + t;
            const int buf = ug >> 11;
            const int idx = ug & 2047;
            const int r = idx >> 5, u = idx & 31;
            const __nv_bfloat16* src = (buf ? hlo_r : hhi_r) + (size_t)(m0 + r) * HDIM + u * 8;
            cp_async16(sbA + (uint32_t)(buf * 32768 + (r * 32 + (u & ~7) + ((u & 7) ^ (r & 7))) * 16), src);
        }
        asm volatile("cp.async.commit_group;" ::: "memory");
        asm volatile("cp.async.wait_group 0;" ::: "memory");   // A + outstanding X
        __syncthreads();

        float acc[4][4];
#pragma unroll
        for (int j = 0; j < 4; ++j)
#pragma unroll
            for (int r = 0; r < 4; ++r) acc[j][r] = 0.f;

        // ---- sync-free MMA loop, shared fragments across 3 split terms ----
#pragma unroll 1
        for (int kc = 0; kc < 4; ++kc) {
#pragma unroll
            for (int ks = 0; ks < 4; ++ks) {
                uint32_t ahi[4], alo[4], bhi[4][2], blo[4][2];
                const uint32_t aoff = (uint32_t)((rA * 32 + kc * 8 + ((ks * 2 + mhi) ^ (rA & 7))) * 16);
                ldm_x4(ahi, sbA + aoff);
                ldm_x4(alo, sbA + 32768 + aoff);
#pragma unroll
                for (int q = 0; q < 4; ++q) {
                    const int r = rB[q];
                    const uint32_t sw = (uint32_t)(((ks * 2 + mB) ^ (r & 7)) * 16);
                    ldm_x2(bhi[q], sbB + (uint32_t)((r * 64 + kc * 8) * 16) + sw);
                    ldm_x2(blo[q], sbB + (uint32_t)((r * 64 + 32 + kc * 8) * 16) + sw);
                }
#pragma unroll
                for (int q = 0; q < 4; ++q) {
                    mma_bf16(acc[q], ahi, bhi[q]);
                    mma_bf16(acc[q], alo, bhi[q]);
                    mma_bf16(acc[q], ahi, blo[q]);
                }
            }
        }

        // ---- fused LSTM cell epilogue ----
#pragma unroll
        for (int h = 0; h < 2; ++h) {
            const int m = m0 + wm * 16 + (lane >> 2) + h * 8;
            const float* xr = sx + (m - m0) * 132;
            float hn[2];
#pragma unroll
            for (int jj = 0; jj < 2; ++jj) {
                const int jl = jl0 + jj;
                const int rs = h * 2 + jj;
                const float gi = acc[0][rs] + xr[jl];
                const float gf = acc[1][rs] + xr[32 + jl];
                const float gg = acc[2][rs] + xr[64 + jl];
                const float go = acc[3][rs] + xr[96 + jl];
                const float iv = 1.f / (1.f + expf(-gi));
                const float fv = 1.f / (1.f + expf(-gf));
                const float gv = tanhf(gg);
                const float ov = 1.f / (1.f + expf(-go));
                const float cn = fv * creg[h][jj] + iv * gv;
                hn[jj] = ov * tanhf(cn);
                creg[h][jj] = cn;
            }
            const int idx = m * HDIM + hcol + jl0;
            const __nv_bfloat16 h0 = __float2bfloat16(hn[0]);
            const __nv_bfloat16 h1 = __float2bfloat16(hn[1]);
            __nv_bfloat162 hhp; hhp.x = h0; hhp.y = h1;
            __nv_bfloat162 hlp;
            hlp.x = __float2bfloat16(hn[0] - __bfloat162float(h0));
            hlp.y = __float2bfloat16(hn[1] - __bfloat162float(h1));
            *(__nv_bfloat162*)&hhi_w[idx] = hhp;
            *(__nv_bfloat162*)&hlo_w[idx] = hlp;
            float2 ov2 = make_float2(hn[0] + img_r[h][0], hn[1] + img_r[h][1]);
            *(float2*)&out_t[idx] = ov2;
        }

        // prefetch next step's xg BEFORE the barrier (static data)
        if (ts + 1 < TSTEPS) {
            __syncthreads();       // all epilogue reads of sx done
            issueX(ts + 1);
        }
    }
}

// ---------------- all prepacking in ONE kernel -------------------------------
#define S_EMB  ((size_t)VOCAB * HDIM)
#define S_W    ((size_t)G4 * HDIM)
#define S_HC   ((size_t)BATCH * HDIM)
#define PREP_TOTAL (S_EMB + 2 * S_W + S_HC + G4)

__global__ void prep_all_kernel(const float* __restrict__ emb,
                                const float* __restrict__ Wih,
                                const float* __restrict__ Whh,
                                const float* __restrict__ bih,
                                const float* __restrict__ bhh)
{
    const size_t i = (size_t)blockIdx.x * 256 + threadIdx.x;
    if (i < S_EMB) {
        const float v = emb[i];
        const __nv_bfloat16 h = __float2bfloat16(v);
        g_ehi[i] = h;
        g_elo[i] = __float2bfloat16(v - __bfloat162float(h));
    } else if (i < S_EMB + 2 * S_W) {
        const size_t ii = i - S_EMB;
        const int which = (int)(ii / S_W);
        const int idx = (int)(ii % S_W);
        const int p = idx >> 8, k = idx & 255;
        const int nt = p >> 7, q = (p >> 5) & 3, j = p & 31;
        const int orig = q * 256 + nt * 32 + j;
        const float* W = which ? Whh : Wih;
        __nv_bfloat16* Wd = which ? g_whh : g_wih;
        const float v = W[orig * 256 + k];
        const __nv_bfloat16 h = __float2bfloat16(v);
        Wd[p * 512 + k] = h;
        Wd[p * 512 + 256 + k] = __float2bfloat16(v - __bfloat162float(h));
    } else if (i < S_EMB + 2 * S_W + S_HC) {
        const int idx = (int)(i - S_EMB - 2 * S_W);
        g_hhi[0][idx] = __float2bfloat16(0.f);
        g_hlo[0][idx] = __float2bfloat16(0.f);
    } else if (i < PREP_TOTAL) {
        const int p = (int)(i - S_EMB - 2 * S_W - S_HC);
        const int nt = p >> 7, q = (p >> 5) & 3, j = p & 31;
        const int orig = q * 256 + nt * 32 + j;
        g_biasp[p] = bih[orig] + bhh[orig];
    }
}

// ---------------- fp32 image GEMM (small) ------------------------------------
__global__ __launch_bounds__(256)
void img_gemm_kernel(const float* __restrict__ A, const float* __restrict__ Bm,
                     float* __restrict__ C, const float* __restrict__ bias)
{
    const int N = HDIM, K = IMGD;
    __shared__ float As[16][64];
    __shared__ float Bs[16][64];
    const int tid = threadIdx.x;
    const int tx = tid & 15, ty = tid >> 4;
    const int m0 = blockIdx.x * 64, n0 = blockIdx.y * 64;
    const int lrow = tid >> 2, lcol4 = (tid & 3) * 4;
    const float* aptr = A + (size_t)(m0 + lrow) * K;
    const float* bptr = Bm + (size_t)(n0 + lrow) * K;
    float acc[4][4];
#pragma unroll
    for (int i = 0; i < 4; i++)
#pragma unroll
        for (int j = 0; j < 4; j++) acc[i][j] = 0.f;
    for (int k0 = 0; k0 < K; k0 += 16) {
        float4 av = *(const float4*)(aptr + k0 + lcol4);
        float4 bv = *(const float4*)(bptr + k0 + lcol4);
        As[lcol4 + 0][lrow] = av.x; As[lcol4 + 1][lrow] = av.y;
        As[lcol4 + 2][lrow] = av.z; As[lcol4 + 3][lrow] = av.w;
        Bs[lcol4 + 0][lrow] = bv.x; Bs[lcol4 + 1][lrow] = bv.y;
        Bs[lcol4 + 2][lrow] = bv.z; Bs[lcol4 + 3][lrow] = bv.w;
        __syncthreads();
#pragma unroll
        for (int k = 0; k < 16; k++) {
            float a[4], b[4];
            *(float4*)a = *(const float4*)&As[k][ty * 4];
            *(float4*)b = *(const float4*)&Bs[k][tx * 4];
#pragma unroll
            for (int i = 0; i < 4; i++)
#pragma unroll
                for (int j = 0; j < 4; j++) acc[i][j] = fmaf(a[i], b[j], acc[i][j]);
        }
        __syncthreads();
    }
#pragma unroll
    for (int i = 0; i < 4; i++)
#pragma unroll
        for (int j = 0; j < 4; j++)
            C[(size_t)(m0 + ty * 4 + i) * N + n0 + tx * 4 + j] =
                fmaxf(acc[i][j] + bias[n0 + tx * 4 + j], 0.f);
}

// ---------------- launcher ---------------------------------------------------
extern "C" void kernel_launch(void* const* d_in, const int* in_sizes, int n_in,
                              void* d_out, int out_size)
{
    const float* img  = (const float*)d_in[0];
    const int*   cap  = (const int*)  d_in[1];
    const float* Wimg = (const float*)d_in[2];
    const float* bimg = (const float*)d_in[3];
    const float* emb  = (const float*)d_in[4];
    const float* Wih  = (const float*)d_in[5];
    const float* Whh  = (const float*)d_in[6];
    const float* bih  = (const float*)d_in[7];
    const float* bhh  = (const float*)d_in[8];
    float* out = (float*)d_out;

    float* p_img;  cudaGetSymbolAddress((void**)&p_img,  g_img);
    float* p_proj; cudaGetSymbolAddress((void**)&p_proj, g_proj);

    cudaFuncSetAttribute(proj_mma_kernel, cudaFuncAttributeMaxDynamicSharedMemorySize, XG_SMEM);
    cudaFuncSetAttribute(lstm_persist_kernel, cudaFuncAttributeMaxDynamicSharedMemorySize, PS_SMEM);

    prep_all_kernel<<<(int)((PREP_TOTAL + 255) / 256), 256>>>(emb, Wih, Whh, bih, bhh);

    {
        dim3 grid(BATCH / 64, HDIM / 64);
        img_gemm_kernel<<<grid, 256>>>(img, Wimg, p_img, bimg);
    }

    {
        dim3 grid(VOCAB / 128, G4 / 128);   // 250 x 8
        proj_mma_kernel<<<grid, 256, XG_SMEM>>>(p_proj);
    }

    lstm_persist_kernel<<<128, 512, PS_SMEM>>>(cap, out);
}

// round 12
// speedup vs baseline: 5.0910x; 1.0471x over previous
#include <cuda_runtime.h>
#include <cuda_bf16.h>
#include <math.h>
#include <stdint.h>

#define HDIM   256
#define BATCH  1024
#define TSTEPS 64
#define IMGD   2048
#define G4     1024
#define VOCAB  32000

// ---------------- device scratch (no allocation allowed) -------------------
__device__ float g_img[BATCH * HDIM];
__device__ float g_proj[(size_t)VOCAB * G4];                 // vocab projection (131MB)
__device__ __nv_bfloat16 g_ehi[(size_t)VOCAB * HDIM];
__device__ __nv_bfloat16 g_elo[(size_t)VOCAB * HDIM];
__device__ __nv_bfloat16 g_wih[G4 * 2 * HDIM];               // [p][0:256]=hi, [256:512]=lo
__device__ __nv_bfloat16 g_whh[G4 * 2 * HDIM];
__device__ float g_biasp[G4];
__device__ __nv_bfloat16 g_hhi[2][BATCH * HDIM];
__device__ __nv_bfloat16 g_hlo[2][BATCH * HDIM];

// grid-barrier state (proven primitive)
__device__ int g_bar_count;
__device__ volatile unsigned g_bar_gen;

// ---------------- helpers ---------------------------------------------------
__device__ __forceinline__ uint32_t smem_u32(const void* p) {
    uint32_t a;
    asm("{ .reg .u64 t; cvta.to.shared.u64 t, %1; cvt.u32.u64 %0, t; }" : "=r"(a) : "l"(p));
    return a;
}
__device__ __forceinline__ void cp_async16(uint32_t saddr, const void* gaddr) {
    asm volatile("cp.async.cg.shared.global [%0], [%1], 16;" :: "r"(saddr), "l"(gaddr));
}
__device__ __forceinline__ void ldm_x4(uint32_t* r, uint32_t addr) {
    asm volatile("ldmatrix.sync.aligned.m8n8.x4.shared.b16 {%0,%1,%2,%3}, [%4];"
                 : "=r"(r[0]), "=r"(r[1]), "=r"(r[2]), "=r"(r[3]) : "r"(addr));
}
__device__ __forceinline__ void mma_bf16(float* d, const uint32_t* a, const uint32_t* b) {
    asm volatile("mma.sync.aligned.m16n8k16.row.col.f32.bf16.bf16.f32 "
                 "{%0,%1,%2,%3}, {%4,%5,%6,%7}, {%8,%9}, {%0,%1,%2,%3};"
                 : "+f"(d[0]), "+f"(d[1]), "+f"(d[2]), "+f"(d[3])
                 : "r"(a[0]), "r"(a[1]), "r"(a[2]), "r"(a[3]), "r"(b[0]), "r"(b[1]));
}

// proven grid barrier (R5/R7/R8)
__device__ __forceinline__ void grid_barrier() {
    __threadfence();
    __syncthreads();
    if (threadIdx.x == 0) {
        unsigned gen = g_bar_gen;
        if (atomicAdd(&g_bar_count, 1) == (int)gridDim.x - 1) {
            g_bar_count = 0;
            __threadfence();
            g_bar_gen = gen + 1;
        } else {
            while (g_bar_gen == gen) __nanosleep(32);
        }
        __threadfence();
    }
    __syncthreads();
}

// ---------------- vocab-projection GEMM (bf16-split MMA) --------------------
// proj[32000,1024] = emb_all @ Wih'^T + biasp. CTA 128x128, 256 thr.
#define STG_BYTES 32768
#define XG_SMEM   (3 * STG_BYTES)

__global__ __launch_bounds__(256)
void proj_mma_kernel(float* __restrict__ Cout)
{
    extern __shared__ __align__(1024) char smem[];
    const uint32_t sbase = smem_u32(smem);
    const int t = threadIdx.x;
    const int lane = t & 31;
    const int wid = t >> 5;
    const int wm = wid >> 2;
    const int wn = wid & 3;
    const int m0 = blockIdx.x * 128;
    const int n0 = blockIdx.y * 128;

    const int lr = t >> 1;
    const int lhalf = t & 1;
    const __nv_bfloat16* a_hi = g_ehi + (size_t)(m0 + lr) * HDIM;
    const __nv_bfloat16* a_lo = g_elo + (size_t)(m0 + lr) * HDIM;
    const __nv_bfloat16* b_row = g_wih + (size_t)(n0 + lr) * (2 * HDIM);

    uint32_t sdst[4];
#pragma unroll
    for (int i = 0; i < 4; ++i) {
        const int w = lhalf * 4 + i;
        sdst[i] = (uint32_t)((lr * 8 + (w ^ (lr & 7))) * 16);
    }

    int rA[4], rB[4];
    const int mhi = lane >> 4;
    const int kq  = lane >> 3;          // 0..3: k-unit selector for B x4
#pragma unroll
    for (int mf = 0; mf < 4; ++mf)
        rA[mf] = wm * 64 + mf * 16 + ((lane >> 3) & 1) * 8 + (lane & 7);
#pragma unroll
    for (int q = 0; q < 4; ++q)
        rB[q] = wn * 32 + q * 8 + (lane & 7);

    float acc[4][4][4];
#pragma unroll
    for (int i = 0; i < 4; ++i)
#pragma unroll
        for (int j = 0; j < 4; ++j)
#pragma unroll
            for (int r = 0; r < 4; ++r) acc[i][j][r] = 0.f;

    auto issue = [&](int c, int s) {
        const int kcol = (c & 3) * 64;
        const __nv_bfloat16* asrc = (((c >> 2) == 1) ? a_lo : a_hi) + kcol;
        const __nv_bfloat16* bsrc = b_row + kcol + (((c >> 2) == 2) ? 256 : 0);
        const uint32_t sa = sbase + s * STG_BYTES;
        const uint32_t sb = sa + 16384;
#pragma unroll
        for (int i = 0; i < 4; ++i) {
            const int e = (lhalf * 4 + i) * 8;
            cp_async16(sa + sdst[i], asrc + e);
            cp_async16(sb + sdst[i], bsrc + e);
        }
        asm volatile("cp.async.commit_group;" ::: "memory");
    };

    issue(0, 0);
    issue(1, 1);

#pragma unroll 1
    for (int c = 0; c < 12; ++c) {
        if (c < 11) asm volatile("cp.async.wait_group 1;" ::: "memory");
        else        asm volatile("cp.async.wait_group 0;" ::: "memory");
        __syncthreads();
        if (c + 2 < 12) issue(c + 2, (c + 2) % 3);

        const uint32_t sa = sbase + (c % 3) * STG_BYTES;
        const uint32_t sb = sa + 16384;
#pragma unroll
        for (int ksp = 0; ksp < 2; ++ksp) {
            uint32_t bfr4[4][4];
#pragma unroll
            for (int q = 0; q < 4; ++q) {
                const int r = rB[q];
                ldm_x4(bfr4[q], sb + (uint32_t)((r * 8 + ((ksp * 4 + kq) ^ (r & 7))) * 16));
            }
#pragma unroll
            for (int ks2 = 0; ks2 < 2; ++ks2) {
                const int ks = ksp * 2 + ks2;
                uint32_t afr[4][4];
#pragma unroll
                for (int mf = 0; mf < 4; ++mf) {
                    const int r = rA[mf];
                    ldm_x4(afr[mf], sa + (uint32_t)((r * 8 + ((ks * 2 + mhi) ^ (r & 7))) * 16));
                }
#pragma unroll
                for (int mf = 0; mf < 4; ++mf)
#pragma unroll
                    for (int q = 0; q < 4; ++q)
                        mma_bf16(acc[mf][q], afr[mf], bfr4[q] + ks2 * 2);
            }
        }
    }

    const int mrow = m0 + wm * 64 + (lane >> 2);
    const int nco  = n0 + wn * 32 + (lane & 3) * 2;
#pragma unroll
    for (int q = 0; q < 4; ++q) {
        const float bp0 = g_biasp[nco + q * 8];
        const float bp1 = g_biasp[nco + q * 8 + 1];
#pragma unroll
        for (int mf = 0; mf < 4; ++mf) {
            const int m = mrow + mf * 16;
            float2 v0 = make_float2(acc[mf][q][0] + bp0, acc[mf][q][1] + bp1);
            float2 v1 = make_float2(acc[mf][q][2] + bp0, acc[mf][q][3] + bp1);
            *(float2*)&Cout[(size_t)m * G4 + nco + q * 8] = v0;
            *(float2*)&Cout[(size_t)(m + 8) * G4 + nco + q * 8] = v1;
        }
    }
}

// ---------------- persistent LSTM recurrence v6 -----------------------------
// 128 CTAs (16 mb x 8 nb), tile 64x128, 512 threads (16 warps: 4 wm x 4 wn).
// Whh resident; h tile loaded per step; xg gathered from g_proj pre-barrier;
// c/img in registers. B fragments via ldmatrix x4 (paired k-halves).
// Grid barrier between steps (proven primitive).
#define PB_BYTES 131072
#define PA_BYTES 65536
#define PX_BYTES 33792               // 64 rows * 132 floats (padded)
#define PS_SMEM  (PB_BYTES + PA_BYTES + PX_BYTES)

__global__ __launch_bounds__(512)
void lstm_persist_kernel(const int* __restrict__ cap, float* __restrict__ out)
{
    extern __shared__ __align__(1024) char smem[];
    const uint32_t sbB = smem_u32(smem);
    const uint32_t sbA = sbB + PB_BYTES;
    const uint32_t sbX = sbA + PA_BYTES;
    float* sx = (float*)(smem + PB_BYTES + PA_BYTES);

    const int t = threadIdx.x;
    const int lane = t & 31;
    const int wid = t >> 5;
    const int wm = wid >> 2;           // 0..3 (16 rows each)
    const int wn = wid & 3;            // 0..3
    const int mb = blockIdx.x & 15;
    const int nb = blockIdx.x >> 4;
    const int m0 = mb * 64;
    const int n0 = nb * 128;
    const int hcol = nb * 32;

    // ---- resident B: Whh permuted rows n0..n0+128, 512 cols (hi|lo) ----
#pragma unroll
    for (int i = 0; i < 16; ++i) {
        const int ug = i * 512 + t;
        const int r = ug >> 6, u = ug & 63;
        cp_async16(sbB + (uint32_t)((r * 64 + (u & ~7) + ((u & 7) ^ (r & 7))) * 16),
                   g_whh + (size_t)(n0 + r) * 512 + u * 8);
    }
    asm volatile("cp.async.commit_group;" ::: "memory");

    const int mhi = lane >> 4;
    const int kq  = lane >> 3;          // 0..3: k-unit selector for B x4
    const int rA = wm * 16 + ((lane >> 3) & 1) * 8 + (lane & 7);
    int rB[4];
#pragma unroll
    for (int q = 0; q < 4; ++q)
        rB[q] = q * 32 + wn * 8 + (lane & 7);

    const int jl0 = wn * 8 + (lane & 3) * 2;

    // ---- per-thread state: c (zeros) and img (4 cells) ----
    float creg[2][2];
    float img_r[2][2];
#pragma unroll
    for (int h = 0; h < 2; ++h) {
        const int m = m0 + wm * 16 + (lane >> 2) + h * 8;
        creg[h][0] = 0.f; creg[h][1] = 0.f;
        img_r[h][0] = g_img[m * HDIM + hcol + jl0];
        img_r[h][1] = g_img[m * HDIM + hcol + jl0 + 1];
    }

    // xg prefetch (gathered proj rows); X tile 64x128 fp32 padded to 132
    auto issueX = [&](int ts) {
        const int* capt = cap + ts * BATCH + m0;
#pragma unroll
        for (int i = 0; i < 4; ++i) {
            const int ug = i * 512 + t;
            const int r = ug >> 5, w = ug & 31;
            const int ci = __ldg(capt + r);
            cp_async16(sbX + (uint32_t)(r * 528 + w * 16),
                       g_proj + (size_t)ci * G4 + n0 + w * 4);
        }
        asm volatile("cp.async.commit_group;" ::: "memory");
    };

    issueX(0);

    asm volatile("cp.async.wait_group 1;" ::: "memory");  // B resident
    __syncthreads();

#pragma unroll 1
    for (int ts = 0; ts < TSTEPS; ++ts) {
        const __nv_bfloat16* hhi_r = g_hhi[ts & 1];
        const __nv_bfloat16* hlo_r = g_hlo[ts & 1];
        __nv_bfloat16* hhi_w = g_hhi[(ts & 1) ^ 1];
        __nv_bfloat16* hlo_w = g_hlo[(ts & 1) ^ 1];
        float* out_t = out + (size_t)ts * BATCH * HDIM;

        if (ts) grid_barrier();

        // ---- load whole A (h hi+lo, 64x256) ----
#pragma unroll
        for (int i = 0; i < 8; ++i) {
            const int ug = i * 512 + t;
            const int buf = ug >> 11;
            const int idx = ug & 2047;
            const int r = idx >> 5, u = idx & 31;
            const __nv_bfloat16* src = (buf ? hlo_r : hhi_r) + (size_t)(m0 + r) * HDIM + u * 8;
            cp_async16(sbA + (uint32_t)(buf * 32768 + (r * 32 + (u & ~7) + ((u & 7) ^ (r & 7))) * 16), src);
        }
        asm volatile("cp.async.commit_group;" ::: "memory");
        asm volatile("cp.async.wait_group 0;" ::: "memory");   // A + outstanding X
        __syncthreads();

        float acc[4][4];
#pragma unroll
        for (int j = 0; j < 4; ++j)
#pragma unroll
            for (int r = 0; r < 4; ++r) acc[j][r] = 0.f;

        // ---- sync-free MMA loop: B x4 paired fragments, 3 split terms ----
#pragma unroll 1
        for (int kc = 0; kc < 4; ++kc) {
#pragma unroll
            for (int ksp = 0; ksp < 2; ++ksp) {
                uint32_t bhi[4][4], blo[4][4];
#pragma unroll
                for (int q = 0; q < 4; ++q) {
                    const int r = rB[q];
                    const uint32_t sw = (uint32_t)(((ksp * 4 + kq) ^ (r & 7)) * 16);
                    ldm_x4(bhi[q], sbB + (uint32_t)((r * 64 + kc * 8) * 16) + sw);
                    ldm_x4(blo[q], sbB + (uint32_t)((r * 64 + 32 + kc * 8) * 16) + sw);
                }
#pragma unroll
                for (int ks2 = 0; ks2 < 2; ++ks2) {
                    const int ks = ksp * 2 + ks2;
                    uint32_t ahi[4], alo[4];
                    const uint32_t aoff = (uint32_t)((rA * 32 + kc * 8 + ((ks * 2 + mhi) ^ (rA & 7))) * 16);
                    ldm_x4(ahi, sbA + aoff);
                    ldm_x4(alo, sbA + 32768 + aoff);
#pragma unroll
                    for (int q = 0; q < 4; ++q) {
                        mma_bf16(acc[q], ahi, bhi[q] + ks2 * 2);
                        mma_bf16(acc[q], alo, bhi[q] + ks2 * 2);
                        mma_bf16(acc[q], ahi, blo[q] + ks2 * 2);
                    }
                }
            }
        }

        // ---- fused LSTM cell epilogue ----
#pragma unroll
        for (int h = 0; h < 2; ++h) {
            const int m = m0 + wm * 16 + (lane >> 2) + h * 8;
            const float* xr = sx + (m - m0) * 132;
            float hn[2];
#pragma unroll
            for (int jj = 0; jj < 2; ++jj) {
                const int jl = jl0 + jj;
                const int rs = h * 2 + jj;
                const float gi = acc[0][rs] + xr[jl];
                const float gf = acc[1][rs] + xr[32 + jl];
                const float gg = acc[2][rs] + xr[64 + jl];
                const float go = acc[3][rs] + xr[96 + jl];
                const float iv = 1.f / (1.f + expf(-gi));
                const float fv = 1.f / (1.f + expf(-gf));
                const float gv = tanhf(gg);
                const float ov = 1.f / (1.f + expf(-go));
                const float cn = fv * creg[h][jj] + iv * gv;
                hn[jj] = ov * tanhf(cn);
                creg[h][jj] = cn;
            }
            const int idx = m * HDIM + hcol + jl0;
            const __nv_bfloat16 h0 = __float2bfloat16(hn[0]);
            const __nv_bfloat16 h1 = __float2bfloat16(hn[1]);
            __nv_bfloat162 hhp; hhp.x = h0; hhp.y = h1;
            __nv_bfloat162 hlp;
            hlp.x = __float2bfloat16(hn[0] - __bfloat162float(h0));
            hlp.y = __float2bfloat16(hn[1] - __bfloat162float(h1));
            *(__nv_bfloat162*)&hhi_w[idx] = hhp;
            *(__nv_bfloat162*)&hlo_w[idx] = hlp;
            float2 ov2 = make_float2(hn[0] + img_r[h][0], hn[1] + img_r[h][1]);
            *(float2*)&out_t[idx] = ov2;
        }

        // prefetch next step's xg BEFORE the barrier (static data)
        if (ts + 1 < TSTEPS) {
            __syncthreads();       // all epilogue reads of sx done
            issueX(ts + 1);
        }
    }
}

// ---------------- all prepacking in ONE kernel -------------------------------
#define S_EMB  ((size_t)VOCAB * HDIM)
#define S_W    ((size_t)G4 * HDIM)
#define S_HC   ((size_t)BATCH * HDIM)
#define PREP_TOTAL (S_EMB + 2 * S_W + S_HC + G4)

__global__ void prep_all_kernel(const float* __restrict__ emb,
                                const float* __restrict__ Wih,
                                const float* __restrict__ Whh,
                                const float* __restrict__ bih,
                                const float* __restrict__ bhh)
{
    const size_t i = (size_t)blockIdx.x * 256 + threadIdx.x;
    if (i < S_EMB) {
        const float v = emb[i];
        const __nv_bfloat16 h = __float2bfloat16(v);
        g_ehi[i] = h;
        g_elo[i] = __float2bfloat16(v - __bfloat162float(h));
    } else if (i < S_EMB + 2 * S_W) {
        const size_t ii = i - S_EMB;
        const int which = (int)(ii / S_W);
        const int idx = (int)(ii % S_W);
        const int p = idx >> 8, k = idx & 255;
        const int nt = p >> 7, q = (p >> 5) & 3, j = p & 31;
        const int orig = q * 256 + nt * 32 + j;
        const float* W = which ? Whh : Wih;
        __nv_bfloat16* Wd = which ? g_whh : g_wih;
        const float v = W[orig * 256 + k];
        const __nv_bfloat16 h = __float2bfloat16(v);
        Wd[p * 512 + k] = h;
        Wd[p * 512 + 256 + k] = __float2bfloat16(v - __bfloat162float(h));
    } else if (i < S_EMB + 2 * S_W + S_HC) {
        const int idx = (int)(i - S_EMB - 2 * S_W);
        g_hhi[0][idx] = __float2bfloat16(0.f);
        g_hlo[0][idx] = __float2bfloat16(0.f);
    } else if (i < PREP_TOTAL) {
        const int p = (int)(i - S_EMB - 2 * S_W - S_HC);
        const int nt = p >> 7, q = (p >> 5) & 3, j = p & 31;
        const int orig = q * 256 + nt * 32 + j;
        g_biasp[p] = bih[orig] + bhh[orig];
    }
}

// ---------------- fp32 image GEMM (small) ------------------------------------
__global__ __launch_bounds__(256)
void img_gemm_kernel(const float* __restrict__ A, const float* __restrict__ Bm,
                     float* __restrict__ C, const float* __restrict__ bias)
{
    const int N = HDIM, K = IMGD;
    __shared__ float As[16][64];
    __shared__ float Bs[16][64];
    const int tid = threadIdx.x;
    const int tx = tid & 15, ty = tid >> 4;
    const int m0 = blockIdx.x * 64, n0 = blockIdx.y * 64;
    const int lrow = tid >> 2, lcol4 = (tid & 3) * 4;
    const float* aptr = A + (size_t)(m0 + lrow) * K;
    const float* bptr = Bm + (size_t)(n0 + lrow) * K;
    float acc[4][4];
#pragma unroll
    for (int i = 0; i < 4; i++)
#pragma unroll
        for (int j = 0; j < 4; j++) acc[i][j] = 0.f;
    for (int k0 = 0; k0 < K; k0 += 16) {
        float4 av = *(const float4*)(aptr + k0 + lcol4);
        float4 bv = *(const float4*)(bptr + k0 + lcol4);
        As[lcol4 + 0][lrow] = av.x; As[lcol4 + 1][lrow] = av.y;
        As[lcol4 + 2][lrow] = av.z; As[lcol4 + 3][lrow] = av.w;
        Bs[lcol4 + 0][lrow] = bv.x; Bs[lcol4 + 1][lrow] = bv.y;
        Bs[lcol4 + 2][lrow] = bv.z; Bs[lcol4 + 3][lrow] = bv.w;
        __syncthreads();
#pragma unroll
        for (int k = 0; k < 16; k++) {
            float a[4], b[4];
            *(float4*)a = *(const float4*)&As[k][ty * 4];
            *(float4*)b = *(const float4*)&Bs[k][tx * 4];
#pragma unroll
            for (int i = 0; i < 4; i++)
#pragma unroll
                for (int j = 0; j < 4; j++) acc[i][j] = fmaf(a[i], b[j], acc[i][j]);
        }
        __syncthreads();
    }
#pragma unroll
    for (int i = 0; i < 4; i++)
#pragma unroll
        for (int j = 0; j < 4; j++)
            C[(size_t)(m0 + ty * 4 + i) * N + n0 + tx * 4 + j] =
                fmaxf(acc[i][j] + bias[n0 + tx * 4 + j], 0.f);
}

// ---------------- launcher ---------------------------------------------------
extern "C" void kernel_launch(void* const* d_in, const int* in_sizes, int n_in,
                              void* d_out, int out_size)
{
    const float* img  = (const float*)d_in[0];
    const int*   cap  = (const int*)  d_in[1];
    const float* Wimg = (const float*)d_in[2];
    const float* bimg = (const float*)d_in[3];
    const float* emb  = (const float*)d_in[4];
    const float* Wih  = (const float*)d_in[5];
    const float* Whh  = (const float*)d_in[6];
    const float* bih  = (const float*)d_in[7];
    const float* bhh  = (const float*)d_in[8];
    float* out = (float*)d_out;

    float* p_img;  cudaGetSymbolAddress((void**)&p_img,  g_img);
    float* p_proj; cudaGetSymbolAddress((void**)&p_proj, g_proj);

    cudaFuncSetAttribute(proj_mma_kernel, cudaFuncAttributeMaxDynamicSharedMemorySize, XG_SMEM);
    cudaFuncSetAttribute(lstm_persist_kernel, cudaFuncAttributeMaxDynamicSharedMemorySize, PS_SMEM);

    prep_all_kernel<<<(int)((PREP_TOTAL + 255) / 256), 256>>>(emb, Wih, Whh, bih, bhh);

    {
        dim3 grid(BATCH / 64, HDIM / 64);
        img_gemm_kernel<<<grid, 256>>>(img, Wimg, p_img, bimg);
    }

    {
        dim3 grid(VOCAB / 128, G4 / 128);   // 250 x 8
        proj_mma_kernel<<<grid, 256, XG_SMEM>>>(p_proj);
    }

    lstm_persist_kernel<<<128, 512, PS_SMEM>>>(cap, out);
}